// round 12
// baseline (speedup 1.0000x reference)
#include <cuda_runtime.h>
#include <cuda_bf16.h>
#include <math.h>
#include <stdint.h>

#define HID   1024
#define EMB   512
#define TLEN  2048
#define G4    4096
#define NCTA  128
#define OSIZE 32000
#define K3E   (3*EMB)
#define K3H   (3*HID)

typedef unsigned long long ull;

// ---------------- scratch ----------------
__device__ float g_xg_enc[(size_t)TLEN * G4];
__device__ float g_xg_dec[(size_t)TLEN * G4];
__device__ float g_hs[(size_t)TLEN * HID];
__device__ ull   g_htag[2][HID];     // (tag:u32 << 32) | (h:f32 bits)
__device__ float g_cenc[HID];
__device__ float g_czero[HID];
__device__ int   g_decidx[TLEN];
__device__ __nv_bfloat16 g_A3e[(size_t)TLEN * K3E];
__device__ __nv_bfloat16 g_A3d[(size_t)TLEN * K3E];
__device__ __nv_bfloat16 g_W3e[(size_t)G4 * K3E];
__device__ __nv_bfloat16 g_W3d[(size_t)G4 * K3E];
__device__ __nv_bfloat16 g_B3o[(size_t)OSIZE * K3H];
__device__ __nv_bfloat16 g_A3h[(size_t)TLEN * K3H];

// ---------------- helpers ----------------
__device__ __forceinline__ uint32_t s2u(const void* p) {
    return (uint32_t)__cvta_generic_to_shared(p);
}
__device__ __forceinline__ void cp16(uint32_t dst, const void* src) {
    asm volatile("cp.async.cg.shared.global [%0], [%1], 16;" :: "r"(dst), "l"(src) : "memory");
}
#define CP_COMMIT() asm volatile("cp.async.commit_group;" ::: "memory")
#define CP_WAIT2()  asm volatile("cp.async.wait_group 2;" ::: "memory")

#define LDSM_X4(r0, r1, r2, r3, addr) \
    asm volatile("ldmatrix.sync.aligned.m8n8.x4.shared.b16 {%0,%1,%2,%3}, [%4];" \
                 : "=r"(r0), "=r"(r1), "=r"(r2), "=r"(r3) : "r"(addr))

#define MMA16816(d, a, b0, b1) \
    asm volatile("mma.sync.aligned.m16n8k16.row.col.f32.bf16.bf16.f32 " \
                 "{%0,%1,%2,%3}, {%4,%5,%6,%7}, {%8,%9}, {%0,%1,%2,%3};" \
                 : "+f"((d)[0]), "+f"((d)[1]), "+f"((d)[2]), "+f"((d)[3]) \
                 : "r"((a)[0]), "r"((a)[1]), "r"((a)[2]), "r"((a)[3]), \
                   "r"(b0), "r"(b1))

#define FMA2(acc, w, h) \
    asm("fma.rn.f32x2 %0, %1, %2, %0;" : "+l"(acc) : "l"(w), "l"(h))
#define ADD2(d, a, b) \
    asm("add.rn.f32x2 %0, %1, %2;" : "=l"(d) : "l"(a), "l"(b))

__device__ __forceinline__ float tanh_apx(float x) {
    float r;
    asm("tanh.approx.f32 %0, %1;" : "=f"(r) : "f"(x));
    return r;
}
__device__ __forceinline__ float sigf(float x) {
    return fmaf(tanh_apx(0.5f * x), 0.5f, 0.5f);
}

static __device__ __forceinline__ uint32_t sw128(uint32_t off) {
    return off ^ ((off >> 3) & 0x70);
}

__device__ __forceinline__ ull ld_acq64(const ull* p) {
    ull v;
    asm volatile("ld.acquire.gpu.global.u64 %0, [%1];" : "=l"(v) : "l"(p) : "memory");
    return v;
}

// ---------------- init kernels ----------------
__global__ void init0_kernel(const int* __restrict__ gt) {
    int i = blockIdx.x * blockDim.x + threadIdx.x;
    if (i < HID) {
        g_htag[0][i] = 0ull;                        // h=0, tag=0 (encoder e=0)
        g_htag[1][i] = 0xFFFFFFFF00000000ull;       // sentinel (never polled)
        g_czero[i] = 0.f;
    }
    if (i < TLEN) g_decidx[i] = (i == 0) ? 1 : gt[i - 1];
}
__global__ void init1_kernel() {
    int i = blockIdx.x * blockDim.x + threadIdx.x;
    if (i < HID) {
        // decoder h0 = enc_c, epoch 2048 (parity 0)
        g_htag[0][i] = ((ull)2048u << 32) | (ull)__float_as_uint(g_cenc[i]);
    }
}

// ---------------- bf16 hi/lo split: mode 0 => [hi|lo|hi], mode 1 => [hi|hi|lo] ----------------
__global__ __launch_bounds__(256)
void conv_split(const float* __restrict__ src, const int* __restrict__ idx,
                __nv_bfloat16* __restrict__ dst, int K, long total, int mode)
{
    long i = ((long)blockIdx.x * blockDim.x + threadIdx.x) * 4;
    if (i >= total) return;
    int r = (int)(i / K);
    int k = (int)(i % K);
    int srow = idx ? idx[r] : r;
    float4 v = *(const float4*)(src + (size_t)srow * K + k);

    __nv_bfloat16 hx = __float2bfloat16_rn(v.x), hy = __float2bfloat16_rn(v.y);
    __nv_bfloat16 hz = __float2bfloat16_rn(v.z), hw = __float2bfloat16_rn(v.w);
    __nv_bfloat16 lx = __float2bfloat16_rn(v.x - __bfloat162float(hx));
    __nv_bfloat16 ly = __float2bfloat16_rn(v.y - __bfloat162float(hy));
    __nv_bfloat16 lz = __float2bfloat16_rn(v.z - __bfloat162float(hz));
    __nv_bfloat16 lw = __float2bfloat16_rn(v.w - __bfloat162float(hw));

    size_t base = (size_t)r * 3 * K;
    __nv_bfloat162 h01 = {hx, hy}, h23 = {hz, hw};
    __nv_bfloat162 l01 = {lx, ly}, l23 = {lz, lw};

    *(__nv_bfloat162*)(dst + base + k)     = h01;
    *(__nv_bfloat162*)(dst + base + k + 2) = h23;
    if (mode == 0) {
        *(__nv_bfloat162*)(dst + base + K + k)       = l01;
        *(__nv_bfloat162*)(dst + base + K + k + 2)   = l23;
        *(__nv_bfloat162*)(dst + base + 2*K + k)     = h01;
        *(__nv_bfloat162*)(dst + base + 2*K + k + 2) = h23;
    } else {
        *(__nv_bfloat162*)(dst + base + K + k)       = h01;
        *(__nv_bfloat162*)(dst + base + K + k + 2)   = h23;
        *(__nv_bfloat162*)(dst + base + 2*K + k)     = l01;
        *(__nv_bfloat162*)(dst + base + 2*K + k + 2) = l23;
    }
}

// ---------------- mma.sync bf16 GEMM (unchanged from R8/R10) ----------------
#define ASTG 16384
#define BSTG 32768
#define STG  (ASTG + BSTG)
#define GEMM_SMEM (4 * STG + 2048)

__global__ __launch_bounds__(256, 1)
void gemm_mma3(const __nv_bfloat16* __restrict__ Ag, const __nv_bfloat16* __restrict__ Bg,
               const float* __restrict__ b1, const float* __restrict__ b2,
               float* __restrict__ C, int Mt, int K3, int Ncols, int GN)
{
    extern __shared__ char smem_raw[];
    const uint32_t sraw = s2u(smem_raw);
    const uint32_t sb0  = (sraw + 1023u) & ~1023u;
    float* sbias = (float*)(smem_raw + (sb0 - sraw) + 4 * STG);

    const int tid  = threadIdx.x;
    const int wid  = tid >> 5;
    const int lane = tid & 31;
    const int NC   = K3 >> 6;

    int gw  = Mt * GN;
    int gid = blockIdx.x / gw;
    int rem = blockIdx.x % gw;
    int m0 = (rem % Mt) * 128;
    int n0 = (gid * GN + rem / Mt) * 256;

    sbias[tid] = b1[n0 + tid] + (b2 ? b2[n0 + tid] : 0.f);

    const int rbase = tid >> 3;
    const int seg   = tid & 7;
    uint32_t swA[4], swB[8];
#pragma unroll
    for (int r = 0; r < 4; r++)
        swA[r] = sw128((uint32_t)(rbase + r * 32) * 128u + (uint32_t)seg * 16u);
#pragma unroll
    for (int r = 0; r < 8; r++)
        swB[r] = sw128((uint32_t)(rbase + r * 32) * 128u + (uint32_t)seg * 16u);
    const __nv_bfloat16* Asrc = Ag + (size_t)(m0 + rbase) * K3 + seg * 8;
    const __nv_bfloat16* Bsrc = Bg + (size_t)(n0 + rbase) * K3 + seg * 8;
    const size_t rstride = (size_t)32 * K3;

    const int wm = wid & 1;
    const int wn = wid >> 1;
    const int arow = wm * 64 + (lane & 15);
    const uint32_t akoff = (uint32_t)(lane >> 4) * 16u;
    const int brow = wn * 64 + ((lane >> 4) & 1) * 8 + (lane & 7);
    const uint32_t bkoff = (uint32_t)((lane >> 3) & 1) * 16u;

    float d[4][8][4];
#pragma unroll
    for (int i = 0; i < 4; i++)
#pragma unroll
        for (int j = 0; j < 8; j++)
#pragma unroll
            for (int q = 0; q < 4; q++) d[i][j][q] = 0.f;

#pragma unroll
    for (int c = 0; c < 3; c++) {
        uint32_t ab = sb0 + c * STG;
        uint32_t bb = ab + ASTG;
#pragma unroll
        for (int r = 0; r < 4; r++)
            cp16(ab + swA[r], Asrc + r * rstride + (size_t)c * 64);
#pragma unroll
        for (int r = 0; r < 8; r++)
            cp16(bb + swB[r], Bsrc + r * rstride + (size_t)c * 64);
        CP_COMMIT();
    }

    for (int c = 0; c < NC; ++c) {
        CP_WAIT2();
        __syncthreads();

        int slot = c & 3;
        uint32_t sA = sb0 + slot * STG;
        uint32_t sB = sA + ASTG;

#pragma unroll
        for (int ks = 0; ks < 4; ks++) {
            uint32_t kb = (uint32_t)ks * 32u;
            uint32_t a[4][4], bq[4][4];
#pragma unroll
            for (int i = 0; i < 4; i++) {
                uint32_t addr = sA + sw128((uint32_t)(arow + 16 * i) * 128u + kb + akoff);
                LDSM_X4(a[i][0], a[i][1], a[i][2], a[i][3], addr);
            }
#pragma unroll
            for (int j = 0; j < 4; j++) {
                uint32_t addr = sB + sw128((uint32_t)(brow + 16 * j) * 128u + kb + bkoff);
                LDSM_X4(bq[j][0], bq[j][1], bq[j][2], bq[j][3], addr);
            }
#pragma unroll
            for (int i = 0; i < 4; i++) {
#pragma unroll
                for (int j = 0; j < 4; j++) {
                    MMA16816(d[i][2 * j],     a[i], bq[j][0], bq[j][1]);
                    MMA16816(d[i][2 * j + 1], a[i], bq[j][2], bq[j][3]);
                }
            }
        }

        int cl = c + 3;
        if (cl < NC) {
            int ls = cl & 3;
            uint32_t ab = sb0 + ls * STG;
            uint32_t bb = ab + ASTG;
#pragma unroll
            for (int r = 0; r < 4; r++)
                cp16(ab + swA[r], Asrc + r * rstride + (size_t)cl * 64);
#pragma unroll
            for (int r = 0; r < 8; r++)
                cp16(bb + swB[r], Bsrc + r * rstride + (size_t)cl * 64);
            CP_COMMIT();
        }
    }

    const int erow = lane >> 2;
    const int ecol = (lane & 3) * 2;
#pragma unroll
    for (int i = 0; i < 4; i++) {
        int r0 = m0 + wm * 64 + i * 16 + erow;
#pragma unroll
        for (int j = 0; j < 8; j++) {
            int cbase = wn * 64 + j * 8 + ecol;
            float bz0 = sbias[cbase], bz1 = sbias[cbase + 1];
            float2 v0 = { d[i][j][0] + bz0, d[i][j][1] + bz1 };
            float2 v1 = { d[i][j][2] + bz0, d[i][j][3] + bz1 };
            *(float2*)(C + (size_t)r0 * Ncols + n0 + cbase)       = v0;
            *(float2*)(C + (size_t)(r0 + 8) * Ncols + n0 + cbase) = v1;
        }
    }
}

// ---------------- persistent LSTM scan v8: dataflow sync, atomic transport ----
// Same as v7 but the tagged h words are moved with morally-strong pairs:
// st.release.gpu.u64 publish / ld.acquire.gpu.u64 poll (same size & address),
// eliminating the mixed-size (64b store vs 128b load) tearing that broke v7.
__global__ __launch_bounds__(256, 1)
void lstm_seq(const float* __restrict__ Whh, const float* __restrict__ xg,
              const float* __restrict__ c0, float* __restrict__ hs_out,
              float* __restrict__ c_out, int T, int e0)
{
    __shared__ ulonglong2 sh2[256];     // h_t (1024 floats)
    __shared__ float sp[2][8][33];      // parity-buffered partials

    const int tid  = threadIdx.x;
    const int warp = tid >> 5;
    const int lane = tid & 31;
    const int cta  = blockIdx.x;
    const int g    = lane >> 3;         // gate 0..3
    const int jj   = lane & 7;          // local hidden unit
    const int row  = g * HID + cta * 8 + jj;

    ulonglong2 w2[32];
    {
        const ulonglong2* wp =
            (const ulonglong2*)(Whh + (size_t)row * HID + warp * 128);
#pragma unroll
        for (int i = 0; i < 32; i++) w2[i] = wp[i];
    }

    float creg = 0.f;
    if (tid < 8) creg = c0[cta * 8 + tid];

    // this thread stages units [4*tid, 4*tid+4) -> sh2[tid]
    const ull* tb0 = &g_htag[0][4 * tid];
    const ull* tb1 = &g_htag[1][4 * tid];
    ull* const outp = &g_htag[0][0];

    // xg prefetch (warp0 lanes only; used in finalize)
    const float* xgp = xg + (size_t)g * HID + cta * 8 + jj;
    float xgv_next = 0.f;
    if (tid < 32) xgv_next = __ldg(xgp);

    for (int t = 0; t < T; ++t) {
        const int e = e0 + t;
        const uint32_t tag = (uint32_t)e;
        const ull* src = (e & 1) ? tb1 : tb0;

        float xgv = xgv_next;
        if (tid < 32 && t + 1 < T)
            xgv_next = __ldg(xgp + (size_t)(t + 1) * G4);

        // poll own 4 units with matched-size acquire loads
        ull w0, w1, wv2, wv3;
        for (;;) {
            w0  = ld_acq64(src);
            w1  = ld_acq64(src + 1);
            wv2 = ld_acq64(src + 2);
            wv3 = ld_acq64(src + 3);
            if ((uint32_t)(w0 >> 32) == tag && (uint32_t)(w1 >> 32) == tag &&
                (uint32_t)(wv2 >> 32) == tag && (uint32_t)(wv3 >> 32) == tag)
                break;
        }
        ulonglong2 pk;
        pk.x = (w0 & 0xFFFFFFFFull) | (w1 << 32);
        pk.y = (wv2 & 0xFFFFFFFFull) | (wv3 << 32);
        sh2[tid] = pk;
        __syncwarp();

        // 128-wide dot, packed f32x2, warp-uniform smem reads (broadcast)
        ull a0 = 0, a1 = 0, a2 = 0, a3 = 0;
        const ulonglong2* hp = sh2 + warp * 32;
#pragma unroll
        for (int j = 0; j < 32; j += 2) {
            ulonglong2 ha = hp[j];
            ulonglong2 hb = hp[j + 1];
            FMA2(a0, w2[j].x, ha.x);
            FMA2(a1, w2[j].y, ha.y);
            FMA2(a2, w2[j + 1].x, hb.x);
            FMA2(a3, w2[j + 1].y, hb.y);
        }
        ull t01, t23, tt;
        ADD2(t01, a0, a1);
        ADD2(t23, a2, a3);
        ADD2(tt, t01, t23);
        uint32_t lo, hi;
        asm("mov.b64 {%0, %1}, %2;" : "=r"(lo), "=r"(hi) : "l"(tt));
        sp[t & 1][warp][lane] = __uint_as_float(lo) + __uint_as_float(hi);
        __syncthreads();                              // partials ready

        if (warp == 0) {
            float s = xgv;
#pragma unroll
            for (int w = 0; w < 8; w++) s += sp[t & 1][w][lane];
            float gi = __shfl_sync(0xffffffffu, s, lane & 7);
            float gf = __shfl_sync(0xffffffffu, s, 8 + (lane & 7));
            float gz = __shfl_sync(0xffffffffu, s, 16 + (lane & 7));
            float go = __shfl_sync(0xffffffffu, s, 24 + (lane & 7));
            if (lane < 8) {
                creg = sigf(gf) * creg + sigf(gi) * tanh_apx(gz);
                float hnew = sigf(go) * tanh_apx(creg);
                int hidx = cta * 8 + lane;
                ull v = ((ull)(uint32_t)(e + 1) << 32)
                      | (ull)__float_as_uint(hnew);
                ull* dst = outp + (size_t)((e + 1) & 1) * HID + hidx;
                asm volatile("st.release.gpu.global.u64 [%0], %1;"
                             :: "l"(dst), "l"(v) : "memory");
                if (hs_out) hs_out[(size_t)t * HID + hidx] = hnew;
                if (c_out && t == T - 1) c_out[hidx] = creg;
            }
        }
        // no trailing sync: sp parity-buffered; sh2 region is warp-private
    }
}

// ---------------- launch ----------------
static void launch_gemm(const __nv_bfloat16* A, const __nv_bfloat16* B,
                        const float* b1, const float* b2, float* C,
                        int M, int N, int K3, int GN)
{
    int Mt = M / 128, Nt = N / 256;
    cudaFuncSetAttribute(gemm_mma3, cudaFuncAttributeMaxDynamicSharedMemorySize, GEMM_SMEM);
    gemm_mma3<<<Mt * Nt, 256, GEMM_SMEM>>>(A, B, b1, b2, C, Mt, K3, N, GN);
}

extern "C" void kernel_launch(void* const* d_in, const int* in_sizes, int n_in,
                              void* d_out, int out_size)
{
    const int*   e1       = (const int*)d_in[0];
    const int*   gt       = (const int*)d_in[1];
    const float* emb_i    = (const float*)d_in[2];
    const float* emb_o    = (const float*)d_in[3];
    const float* enc_Wih  = (const float*)d_in[4];
    const float* enc_Whh  = (const float*)d_in[5];
    const float* enc_bih  = (const float*)d_in[6];
    const float* enc_bhh  = (const float*)d_in[7];
    const float* dec_Wih  = (const float*)d_in[8];
    const float* dec_Whh  = (const float*)d_in[9];
    const float* dec_bih  = (const float*)d_in[10];
    const float* dec_bhh  = (const float*)d_in[11];
    const float* outW     = (const float*)d_in[12];
    const float* outb     = (const float*)d_in[13];
    float*       out      = (float*)d_out;

    float *xge, *xgd, *hs, *cenc, *czero;
    int* didx;
    __nv_bfloat16 *a3e, *a3d, *w3e, *w3d, *b3o, *a3h;
    cudaGetSymbolAddress((void**)&xge,   g_xg_enc);
    cudaGetSymbolAddress((void**)&xgd,   g_xg_dec);
    cudaGetSymbolAddress((void**)&hs,    g_hs);
    cudaGetSymbolAddress((void**)&cenc,  g_cenc);
    cudaGetSymbolAddress((void**)&czero, g_czero);
    cudaGetSymbolAddress((void**)&didx,  g_decidx);
    cudaGetSymbolAddress((void**)&a3e,   g_A3e);
    cudaGetSymbolAddress((void**)&a3d,   g_A3d);
    cudaGetSymbolAddress((void**)&w3e,   g_W3e);
    cudaGetSymbolAddress((void**)&w3d,   g_W3d);
    cudaGetSymbolAddress((void**)&b3o,   g_B3o);
    cudaGetSymbolAddress((void**)&a3h,   g_A3h);

    init0_kernel<<<8, 256>>>(gt);

    // bf16x3 conversions
    {
        long t1 = (long)G4 * EMB;
        conv_split<<<(int)(t1 / 4 / 256), 256>>>(enc_Wih, nullptr, w3e, EMB, t1, 1);
        conv_split<<<(int)(t1 / 4 / 256), 256>>>(dec_Wih, nullptr, w3d, EMB, t1, 1);
        long t2 = (long)OSIZE * HID;
        conv_split<<<(int)(t2 / 4 / 256), 256>>>(outW, nullptr, b3o, HID, t2, 1);
        long t3 = (long)TLEN * EMB;
        conv_split<<<(int)(t3 / 4 / 256), 256>>>(emb_i, e1,   a3e, EMB, t3, 0);
        conv_split<<<(int)(t3 / 4 / 256), 256>>>(emb_o, didx, a3d, EMB, t3, 0);
    }

    // x-gates
    launch_gemm(a3e, w3e, enc_bih, enc_bhh, xge, TLEN, G4, K3E, 16);
    launch_gemm(a3d, w3d, dec_bih, dec_bhh, xgd, TLEN, G4, K3E, 16);

    // encoder scan: epochs 0..2047
    lstm_seq<<<NCTA, 256>>>(enc_Whh, xge, czero, nullptr, cenc, TLEN, 0);
    init1_kernel<<<4, 256>>>();
    // decoder scan: epochs 2048..4095
    lstm_seq<<<NCTA, 256>>>(dec_Whh, xgd, cenc, hs, nullptr, TLEN, TLEN);

    // logits
    {
        long t4 = (long)TLEN * HID;
        conv_split<<<(int)(t4 / 4 / 256), 256>>>(hs, nullptr, a3h, HID, t4, 0);
    }
    launch_gemm(a3h, b3o, outb, nullptr, out, TLEN, OSIZE, K3H, 25);
}

// round 13
// speedup vs baseline: 1.3520x; 1.3520x over previous
#include <cuda_runtime.h>
#include <cuda_bf16.h>
#include <math.h>
#include <stdint.h>

#define HID   1024
#define EMB   512
#define TLEN  2048
#define G4    4096
#define NCTA  128
#define OSIZE 32000
#define K3E   (3*EMB)
#define K3H   (3*HID)

typedef unsigned long long ull;

// ---------------- scratch ----------------
__device__ float g_xg_enc[(size_t)TLEN * G4];
__device__ float g_xg_dec[(size_t)TLEN * G4];
__device__ float g_hs[(size_t)TLEN * HID];
__device__ float g_hbuf[2][HID];
__device__ float g_cenc[HID];
__device__ float g_czero[HID];
__device__ int   g_decidx[TLEN];
__device__ unsigned g_ctr;
__device__ __nv_bfloat16 g_A3e[(size_t)TLEN * K3E];
__device__ __nv_bfloat16 g_A3d[(size_t)TLEN * K3E];
__device__ __nv_bfloat16 g_W3e[(size_t)G4 * K3E];
__device__ __nv_bfloat16 g_W3d[(size_t)G4 * K3E];
__device__ __nv_bfloat16 g_B3o[(size_t)OSIZE * K3H];
__device__ __nv_bfloat16 g_A3h[(size_t)TLEN * K3H];

// ---------------- helpers ----------------
__device__ __forceinline__ uint32_t s2u(const void* p) {
    return (uint32_t)__cvta_generic_to_shared(p);
}
__device__ __forceinline__ void cp16(uint32_t dst, const void* src) {
    asm volatile("cp.async.cg.shared.global [%0], [%1], 16;" :: "r"(dst), "l"(src) : "memory");
}
#define CP_COMMIT() asm volatile("cp.async.commit_group;" ::: "memory")
#define CP_WAIT2()  asm volatile("cp.async.wait_group 2;" ::: "memory")

#define LDSM_X4(r0, r1, r2, r3, addr) \
    asm volatile("ldmatrix.sync.aligned.m8n8.x4.shared.b16 {%0,%1,%2,%3}, [%4];" \
                 : "=r"(r0), "=r"(r1), "=r"(r2), "=r"(r3) : "r"(addr))

#define MMA16816(d, a, b0, b1) \
    asm volatile("mma.sync.aligned.m16n8k16.row.col.f32.bf16.bf16.f32 " \
                 "{%0,%1,%2,%3}, {%4,%5,%6,%7}, {%8,%9}, {%0,%1,%2,%3};" \
                 : "+f"((d)[0]), "+f"((d)[1]), "+f"((d)[2]), "+f"((d)[3]) \
                 : "r"((a)[0]), "r"((a)[1]), "r"((a)[2]), "r"((a)[3]), \
                   "r"(b0), "r"(b1))

#define FMA2(acc, w, h) \
    asm("fma.rn.f32x2 %0, %1, %2, %0;" : "+l"(acc) : "l"(w), "l"(h))
#define ADD2(d, a, b) \
    asm("add.rn.f32x2 %0, %1, %2;" : "=l"(d) : "l"(a), "l"(b))

__device__ __forceinline__ float tanh_apx(float x) {
    float r;
    asm("tanh.approx.f32 %0, %1;" : "=f"(r) : "f"(x));
    return r;
}
__device__ __forceinline__ float sigf(float x) {
    return fmaf(tanh_apx(0.5f * x), 0.5f, 0.5f);
}

static __device__ __forceinline__ uint32_t sw128(uint32_t off) {
    return off ^ ((off >> 3) & 0x70);
}

// ---------------- init kernels ----------------
__global__ void init0_kernel(const int* __restrict__ gt) {
    int i = blockIdx.x * blockDim.x + threadIdx.x;
    if (i == 0) g_ctr = 0u;
    if (i < HID) { g_hbuf[0][i] = 0.f; g_hbuf[1][i] = 0.f; g_czero[i] = 0.f; }
    if (i < TLEN) g_decidx[i] = (i == 0) ? 1 : gt[i - 1];
}
__global__ void init1_kernel() {
    int i = blockIdx.x * blockDim.x + threadIdx.x;
    if (i == 0) g_ctr = 0u;
    if (i < HID) g_hbuf[0][i] = g_cenc[i];
}

// ---------------- bf16 hi/lo split: mode 0 => [hi|lo|hi], mode 1 => [hi|hi|lo] ----------------
__global__ __launch_bounds__(256)
void conv_split(const float* __restrict__ src, const int* __restrict__ idx,
                __nv_bfloat16* __restrict__ dst, int K, long total, int mode)
{
    long i = ((long)blockIdx.x * blockDim.x + threadIdx.x) * 4;
    if (i >= total) return;
    int r = (int)(i / K);
    int k = (int)(i % K);
    int srow = idx ? idx[r] : r;
    float4 v = *(const float4*)(src + (size_t)srow * K + k);

    __nv_bfloat16 hx = __float2bfloat16_rn(v.x), hy = __float2bfloat16_rn(v.y);
    __nv_bfloat16 hz = __float2bfloat16_rn(v.z), hw = __float2bfloat16_rn(v.w);
    __nv_bfloat16 lx = __float2bfloat16_rn(v.x - __bfloat162float(hx));
    __nv_bfloat16 ly = __float2bfloat16_rn(v.y - __bfloat162float(hy));
    __nv_bfloat16 lz = __float2bfloat16_rn(v.z - __bfloat162float(hz));
    __nv_bfloat16 lw = __float2bfloat16_rn(v.w - __bfloat162float(hw));

    size_t base = (size_t)r * 3 * K;
    __nv_bfloat162 h01 = {hx, hy}, h23 = {hz, hw};
    __nv_bfloat162 l01 = {lx, ly}, l23 = {lz, lw};

    *(__nv_bfloat162*)(dst + base + k)     = h01;
    *(__nv_bfloat162*)(dst + base + k + 2) = h23;
    if (mode == 0) {
        *(__nv_bfloat162*)(dst + base + K + k)       = l01;
        *(__nv_bfloat162*)(dst + base + K + k + 2)   = l23;
        *(__nv_bfloat162*)(dst + base + 2*K + k)     = h01;
        *(__nv_bfloat162*)(dst + base + 2*K + k + 2) = h23;
    } else {
        *(__nv_bfloat162*)(dst + base + K + k)       = h01;
        *(__nv_bfloat162*)(dst + base + K + k + 2)   = h23;
        *(__nv_bfloat162*)(dst + base + 2*K + k)     = l01;
        *(__nv_bfloat162*)(dst + base + 2*K + k + 2) = l23;
    }
}

// ---------------- mma.sync bf16 GEMM (unchanged from R8/R10) ----------------
#define ASTG 16384
#define BSTG 32768
#define STG  (ASTG + BSTG)
#define GEMM_SMEM (4 * STG + 2048)

__global__ __launch_bounds__(256, 1)
void gemm_mma3(const __nv_bfloat16* __restrict__ Ag, const __nv_bfloat16* __restrict__ Bg,
               const float* __restrict__ b1, const float* __restrict__ b2,
               float* __restrict__ C, int Mt, int K3, int Ncols, int GN)
{
    extern __shared__ char smem_raw[];
    const uint32_t sraw = s2u(smem_raw);
    const uint32_t sb0  = (sraw + 1023u) & ~1023u;
    float* sbias = (float*)(smem_raw + (sb0 - sraw) + 4 * STG);

    const int tid  = threadIdx.x;
    const int wid  = tid >> 5;
    const int lane = tid & 31;
    const int NC   = K3 >> 6;

    int gw  = Mt * GN;
    int gid = blockIdx.x / gw;
    int rem = blockIdx.x % gw;
    int m0 = (rem % Mt) * 128;
    int n0 = (gid * GN + rem / Mt) * 256;

    sbias[tid] = b1[n0 + tid] + (b2 ? b2[n0 + tid] : 0.f);

    const int rbase = tid >> 3;
    const int seg   = tid & 7;
    uint32_t swA[4], swB[8];
#pragma unroll
    for (int r = 0; r < 4; r++)
        swA[r] = sw128((uint32_t)(rbase + r * 32) * 128u + (uint32_t)seg * 16u);
#pragma unroll
    for (int r = 0; r < 8; r++)
        swB[r] = sw128((uint32_t)(rbase + r * 32) * 128u + (uint32_t)seg * 16u);
    const __nv_bfloat16* Asrc = Ag + (size_t)(m0 + rbase) * K3 + seg * 8;
    const __nv_bfloat16* Bsrc = Bg + (size_t)(n0 + rbase) * K3 + seg * 8;
    const size_t rstride = (size_t)32 * K3;

    const int wm = wid & 1;
    const int wn = wid >> 1;
    const int arow = wm * 64 + (lane & 15);
    const uint32_t akoff = (uint32_t)(lane >> 4) * 16u;
    const int brow = wn * 64 + ((lane >> 4) & 1) * 8 + (lane & 7);
    const uint32_t bkoff = (uint32_t)((lane >> 3) & 1) * 16u;

    float d[4][8][4];
#pragma unroll
    for (int i = 0; i < 4; i++)
#pragma unroll
        for (int j = 0; j < 8; j++)
#pragma unroll
            for (int q = 0; q < 4; q++) d[i][j][q] = 0.f;

#pragma unroll
    for (int c = 0; c < 3; c++) {
        uint32_t ab = sb0 + c * STG;
        uint32_t bb = ab + ASTG;
#pragma unroll
        for (int r = 0; r < 4; r++)
            cp16(ab + swA[r], Asrc + r * rstride + (size_t)c * 64);
#pragma unroll
        for (int r = 0; r < 8; r++)
            cp16(bb + swB[r], Bsrc + r * rstride + (size_t)c * 64);
        CP_COMMIT();
    }

    for (int c = 0; c < NC; ++c) {
        CP_WAIT2();
        __syncthreads();

        int slot = c & 3;
        uint32_t sA = sb0 + slot * STG;
        uint32_t sB = sA + ASTG;

#pragma unroll
        for (int ks = 0; ks < 4; ks++) {
            uint32_t kb = (uint32_t)ks * 32u;
            uint32_t a[4][4], bq[4][4];
#pragma unroll
            for (int i = 0; i < 4; i++) {
                uint32_t addr = sA + sw128((uint32_t)(arow + 16 * i) * 128u + kb + akoff);
                LDSM_X4(a[i][0], a[i][1], a[i][2], a[i][3], addr);
            }
#pragma unroll
            for (int j = 0; j < 4; j++) {
                uint32_t addr = sB + sw128((uint32_t)(brow + 16 * j) * 128u + kb + bkoff);
                LDSM_X4(bq[j][0], bq[j][1], bq[j][2], bq[j][3], addr);
            }
#pragma unroll
            for (int i = 0; i < 4; i++) {
#pragma unroll
                for (int j = 0; j < 4; j++) {
                    MMA16816(d[i][2 * j],     a[i], bq[j][0], bq[j][1]);
                    MMA16816(d[i][2 * j + 1], a[i], bq[j][2], bq[j][3]);
                }
            }
        }

        int cl = c + 3;
        if (cl < NC) {
            int ls = cl & 3;
            uint32_t ab = sb0 + ls * STG;
            uint32_t bb = ab + ASTG;
#pragma unroll
            for (int r = 0; r < 4; r++)
                cp16(ab + swA[r], Asrc + r * rstride + (size_t)cl * 64);
#pragma unroll
            for (int r = 0; r < 8; r++)
                cp16(bb + swB[r], Bsrc + r * rstride + (size_t)cl * 64);
            CP_COMMIT();
        }
    }

    const int erow = lane >> 2;
    const int ecol = (lane & 3) * 2;
#pragma unroll
    for (int i = 0; i < 4; i++) {
        int r0 = m0 + wm * 64 + i * 16 + erow;
#pragma unroll
        for (int j = 0; j < 8; j++) {
            int cbase = wn * 64 + j * 8 + ecol;
            float bz0 = sbias[cbase], bz1 = sbias[cbase + 1];
            float2 v0 = { d[i][j][0] + bz0, d[i][j][1] + bz1 };
            float2 v1 = { d[i][j][2] + bz0, d[i][j][3] + bz1 };
            *(float2*)(C + (size_t)r0 * Ncols + n0 + cbase)       = v0;
            *(float2*)(C + (size_t)(r0 + 8) * Ncols + n0 + cbase) = v1;
        }
    }
}

// ---------------- persistent LSTM scan v9 ----------------
// R10 structure (1.54us/step champion) with two latency cuts:
//  (1) post-staging block sync -> __syncwarp (sh2 is warp-private)
//  (2) arrival via atom.acq_rel returning old value: the LAST-arriving CTA
//      (the critical-path one) skips the spin entirely.
__global__ __launch_bounds__(256, 1)
void lstm_seq(const float* __restrict__ Whh, const float* __restrict__ xg,
              const float* __restrict__ c0, float* __restrict__ hs_out,
              float* __restrict__ c_out, int T)
{
    __shared__ ulonglong2 sh2[256];   // h_t (1024 floats)
    __shared__ float sp[8][33];       // per-warp partials

    const int tid  = threadIdx.x;
    const int warp = tid >> 5;
    const int lane = tid & 31;
    const int cta  = blockIdx.x;
    const int g    = lane >> 3;       // gate 0..3
    const int jj   = lane & 7;        // local hidden unit
    const int row  = g * HID + cta * 8 + jj;

    ulonglong2 w2[32];
    {
        const ulonglong2* wp =
            (const ulonglong2*)(Whh + (size_t)row * HID + warp * 128);
#pragma unroll
        for (int i = 0; i < 32; i++) w2[i] = wp[i];
    }

    float creg = 0.f;
    if (tid < 8) creg = c0[cta * 8 + tid];
    unsigned* ctr = &g_ctr;

    // xg prefetch (warp0 lanes; consumed in finalize)
    const float* xgp = xg + (size_t)g * HID + cta * 8 + jj;
    float xgv_next = 0.f;
    if (tid < 32) xgv_next = __ldg(xgp);

    for (int t = 0; t < T; ++t) {
        // stage h_t into smem (L1 bypass; sh2 region is warp-private)
        sh2[tid] = __ldcg(((const ulonglong2*)g_hbuf[t & 1]) + tid);
        float xgv = xgv_next;
        if (tid < 32 && t + 1 < T)
            xgv_next = __ldg(xgp + (size_t)(t + 1) * G4);
        __syncwarp();                                 // (A') warp-local staging

        // 128-wide dot, packed f32x2, warp-uniform smem reads (broadcast)
        ull a0 = 0, a1 = 0, a2 = 0, a3 = 0;
        const ulonglong2* hp = sh2 + warp * 32;
#pragma unroll
        for (int j = 0; j < 32; j += 2) {
            ulonglong2 ha = hp[j];
            ulonglong2 hb = hp[j + 1];
            FMA2(a0, w2[j].x, ha.x);
            FMA2(a1, w2[j].y, ha.y);
            FMA2(a2, w2[j + 1].x, hb.x);
            FMA2(a3, w2[j + 1].y, hb.y);
        }
        ull t01, t23, tt;
        ADD2(t01, a0, a1);
        ADD2(t23, a2, a3);
        ADD2(tt, t01, t23);
        uint32_t lo, hi;
        asm("mov.b64 {%0, %1}, %2;" : "=r"(lo), "=r"(hi) : "l"(tt));
        sp[warp][lane] = __uint_as_float(lo) + __uint_as_float(hi);
        __syncthreads();                              // (B) partials ready

        if (warp == 0) {
            float s = xgv;
#pragma unroll
            for (int w = 0; w < 8; w++) s += sp[w][lane];
            float gi = __shfl_sync(0xffffffffu, s, lane & 7);
            float gf = __shfl_sync(0xffffffffu, s, 8 + (lane & 7));
            float gz = __shfl_sync(0xffffffffu, s, 16 + (lane & 7));
            float go = __shfl_sync(0xffffffffu, s, 24 + (lane & 7));
            if (lane < 8) {
                creg = sigf(gf) * creg + sigf(gi) * tanh_apx(gz);
                float hnew = sigf(go) * tanh_apx(creg);
                int hidx = cta * 8 + lane;
                g_hbuf[(t + 1) & 1][hidx] = hnew;
                if (hs_out) hs_out[(size_t)t * HID + hidx] = hnew;
                if (c_out && t == T - 1) c_out[hidx] = creg;
            }
            __syncwarp();
            if (lane == 0) {
                // arrival with returned old count: last arriver skips the spin
                unsigned old;
                asm volatile("atom.acq_rel.gpu.global.add.u32 %0, [%1], 1;"
                             : "=r"(old) : "l"(ctr) : "memory");
                unsigned tgt = (unsigned)(t + 1) * (unsigned)NCTA;
                if (old + 1u != tgt) {
                    unsigned v;
                    do {
                        asm volatile("ld.acquire.gpu.global.u32 %0, [%1];"
                                     : "=r"(v) : "l"(ctr) : "memory");
                    } while (v < tgt);
                }
            }
        }
        __syncthreads();                              // (C) barrier done
    }
}

// ---------------- launch ----------------
static void launch_gemm(const __nv_bfloat16* A, const __nv_bfloat16* B,
                        const float* b1, const float* b2, float* C,
                        int M, int N, int K3, int GN)
{
    int Mt = M / 128, Nt = N / 256;
    cudaFuncSetAttribute(gemm_mma3, cudaFuncAttributeMaxDynamicSharedMemorySize, GEMM_SMEM);
    gemm_mma3<<<Mt * Nt, 256, GEMM_SMEM>>>(A, B, b1, b2, C, Mt, K3, N, GN);
}

extern "C" void kernel_launch(void* const* d_in, const int* in_sizes, int n_in,
                              void* d_out, int out_size)
{
    const int*   e1       = (const int*)d_in[0];
    const int*   gt       = (const int*)d_in[1];
    const float* emb_i    = (const float*)d_in[2];
    const float* emb_o    = (const float*)d_in[3];
    const float* enc_Wih  = (const float*)d_in[4];
    const float* enc_Whh  = (const float*)d_in[5];
    const float* enc_bih  = (const float*)d_in[6];
    const float* enc_bhh  = (const float*)d_in[7];
    const float* dec_Wih  = (const float*)d_in[8];
    const float* dec_Whh  = (const float*)d_in[9];
    const float* dec_bih  = (const float*)d_in[10];
    const float* dec_bhh  = (const float*)d_in[11];
    const float* outW     = (const float*)d_in[12];
    const float* outb     = (const float*)d_in[13];
    float*       out      = (float*)d_out;

    float *xge, *xgd, *hs, *cenc, *czero;
    int* didx;
    __nv_bfloat16 *a3e, *a3d, *w3e, *w3d, *b3o, *a3h;
    cudaGetSymbolAddress((void**)&xge,   g_xg_enc);
    cudaGetSymbolAddress((void**)&xgd,   g_xg_dec);
    cudaGetSymbolAddress((void**)&hs,    g_hs);
    cudaGetSymbolAddress((void**)&cenc,  g_cenc);
    cudaGetSymbolAddress((void**)&czero, g_czero);
    cudaGetSymbolAddress((void**)&didx,  g_decidx);
    cudaGetSymbolAddress((void**)&a3e,   g_A3e);
    cudaGetSymbolAddress((void**)&a3d,   g_A3d);
    cudaGetSymbolAddress((void**)&w3e,   g_W3e);
    cudaGetSymbolAddress((void**)&w3d,   g_W3d);
    cudaGetSymbolAddress((void**)&b3o,   g_B3o);
    cudaGetSymbolAddress((void**)&a3h,   g_A3h);

    init0_kernel<<<8, 256>>>(gt);

    // bf16x3 conversions
    {
        long t1 = (long)G4 * EMB;
        conv_split<<<(int)(t1 / 4 / 256), 256>>>(enc_Wih, nullptr, w3e, EMB, t1, 1);
        conv_split<<<(int)(t1 / 4 / 256), 256>>>(dec_Wih, nullptr, w3d, EMB, t1, 1);
        long t2 = (long)OSIZE * HID;
        conv_split<<<(int)(t2 / 4 / 256), 256>>>(outW, nullptr, b3o, HID, t2, 1);
        long t3 = (long)TLEN * EMB;
        conv_split<<<(int)(t3 / 4 / 256), 256>>>(emb_i, e1,   a3e, EMB, t3, 0);
        conv_split<<<(int)(t3 / 4 / 256), 256>>>(emb_o, didx, a3d, EMB, t3, 0);
    }

    // x-gates
    launch_gemm(a3e, w3e, enc_bih, enc_bhh, xge, TLEN, G4, K3E, 16);
    launch_gemm(a3d, w3d, dec_bih, dec_bhh, xgd, TLEN, G4, K3E, 16);

    // encoder scan
    lstm_seq<<<NCTA, 256>>>(enc_Whh, xge, czero, nullptr, cenc, TLEN);
    init1_kernel<<<4, 256>>>();
    // decoder scan
    lstm_seq<<<NCTA, 256>>>(dec_Whh, xgd, cenc, hs, nullptr, TLEN);

    // logits
    {
        long t4 = (long)TLEN * HID;
        conv_split<<<(int)(t4 / 4 / 256), 256>>>(hs, nullptr, a3h, HID, t4, 0);
    }
    launch_gemm(a3h, b3o, outb, nullptr, out, TLEN, OSIZE, K3H, 25);
}

// round 14
// speedup vs baseline: 1.3679x; 1.0118x over previous
#include <cuda_runtime.h>
#include <cuda_bf16.h>
#include <math.h>
#include <stdint.h>

#define HID   1024
#define EMB   512
#define TLEN  2048
#define G4    4096
#define NCTA  128
#define OSIZE 32000
#define K3E   (3*EMB)
#define K3H   (3*HID)

typedef unsigned long long ull;

// ---------------- scratch ----------------
__device__ float g_xg_enc[(size_t)TLEN * G4];
__device__ float g_xg_dec[(size_t)TLEN * G4];
__device__ float g_hbuf[2][HID];
__device__ float g_cenc[HID];
__device__ float g_czero[HID];
__device__ int   g_decidx[TLEN];
__device__ unsigned g_ctr;
__device__ __nv_bfloat16 g_A3e[(size_t)TLEN * K3E];
__device__ __nv_bfloat16 g_A3d[(size_t)TLEN * K3E];
__device__ __nv_bfloat16 g_W3e[(size_t)G4 * K3E];
__device__ __nv_bfloat16 g_W3d[(size_t)G4 * K3E];
__device__ __nv_bfloat16 g_B3o[(size_t)OSIZE * K3H];
__device__ __nv_bfloat16 g_A3h[(size_t)TLEN * K3H];

// ---------------- helpers ----------------
__device__ __forceinline__ uint32_t s2u(const void* p) {
    return (uint32_t)__cvta_generic_to_shared(p);
}
__device__ __forceinline__ void cp16(uint32_t dst, const void* src) {
    asm volatile("cp.async.cg.shared.global [%0], [%1], 16;" :: "r"(dst), "l"(src) : "memory");
}
#define CP_COMMIT() asm volatile("cp.async.commit_group;" ::: "memory")
#define CP_WAIT2()  asm volatile("cp.async.wait_group 2;" ::: "memory")

#define LDSM_X4(r0, r1, r2, r3, addr) \
    asm volatile("ldmatrix.sync.aligned.m8n8.x4.shared.b16 {%0,%1,%2,%3}, [%4];" \
                 : "=r"(r0), "=r"(r1), "=r"(r2), "=r"(r3) : "r"(addr))

#define MMA16816(d, a, b0, b1) \
    asm volatile("mma.sync.aligned.m16n8k16.row.col.f32.bf16.bf16.f32 " \
                 "{%0,%1,%2,%3}, {%4,%5,%6,%7}, {%8,%9}, {%0,%1,%2,%3};" \
                 : "+f"((d)[0]), "+f"((d)[1]), "+f"((d)[2]), "+f"((d)[3]) \
                 : "r"((a)[0]), "r"((a)[1]), "r"((a)[2]), "r"((a)[3]), \
                   "r"(b0), "r"(b1))

#define FMA2(acc, w, h) \
    asm("fma.rn.f32x2 %0, %1, %2, %0;" : "+l"(acc) : "l"(w), "l"(h))
#define ADD2(d, a, b) \
    asm("add.rn.f32x2 %0, %1, %2;" : "=l"(d) : "l"(a), "l"(b))

__device__ __forceinline__ float tanh_apx(float x) {
    float r;
    asm("tanh.approx.f32 %0, %1;" : "=f"(r) : "f"(x));
    return r;
}
__device__ __forceinline__ float sigf(float x) {
    return fmaf(tanh_apx(0.5f * x), 0.5f, 0.5f);
}

static __device__ __forceinline__ uint32_t sw128(uint32_t off) {
    return off ^ ((off >> 3) & 0x70);
}

// ---------------- init kernels ----------------
__global__ void init0_kernel(const int* __restrict__ gt) {
    int i = blockIdx.x * blockDim.x + threadIdx.x;
    if (i == 0) g_ctr = 0u;
    if (i < HID) { g_hbuf[0][i] = 0.f; g_hbuf[1][i] = 0.f; g_czero[i] = 0.f; }
    if (i < TLEN) g_decidx[i] = (i == 0) ? 1 : gt[i - 1];
}
__global__ void init1_kernel() {
    int i = blockIdx.x * blockDim.x + threadIdx.x;
    if (i == 0) g_ctr = 0u;
    if (i < HID) g_hbuf[0][i] = g_cenc[i];
}

// ---------------- bf16 hi/lo split: mode 0 => [hi|lo|hi], mode 1 => [hi|hi|lo] ----------------
__global__ __launch_bounds__(256)
void conv_split(const float* __restrict__ src, const int* __restrict__ idx,
                __nv_bfloat16* __restrict__ dst, int K, long total, int mode)
{
    long i = ((long)blockIdx.x * blockDim.x + threadIdx.x) * 4;
    if (i >= total) return;
    int r = (int)(i / K);
    int k = (int)(i % K);
    int srow = idx ? idx[r] : r;
    float4 v = *(const float4*)(src + (size_t)srow * K + k);

    __nv_bfloat16 hx = __float2bfloat16_rn(v.x), hy = __float2bfloat16_rn(v.y);
    __nv_bfloat16 hz = __float2bfloat16_rn(v.z), hw = __float2bfloat16_rn(v.w);
    __nv_bfloat16 lx = __float2bfloat16_rn(v.x - __bfloat162float(hx));
    __nv_bfloat16 ly = __float2bfloat16_rn(v.y - __bfloat162float(hy));
    __nv_bfloat16 lz = __float2bfloat16_rn(v.z - __bfloat162float(hz));
    __nv_bfloat16 lw = __float2bfloat16_rn(v.w - __bfloat162float(hw));

    size_t base = (size_t)r * 3 * K;
    __nv_bfloat162 h01 = {hx, hy}, h23 = {hz, hw};
    __nv_bfloat162 l01 = {lx, ly}, l23 = {lz, lw};

    *(__nv_bfloat162*)(dst + base + k)     = h01;
    *(__nv_bfloat162*)(dst + base + k + 2) = h23;
    if (mode == 0) {
        *(__nv_bfloat162*)(dst + base + K + k)       = l01;
        *(__nv_bfloat162*)(dst + base + K + k + 2)   = l23;
        *(__nv_bfloat162*)(dst + base + 2*K + k)     = h01;
        *(__nv_bfloat162*)(dst + base + 2*K + k + 2) = h23;
    } else {
        *(__nv_bfloat162*)(dst + base + K + k)       = h01;
        *(__nv_bfloat162*)(dst + base + K + k + 2)   = h23;
        *(__nv_bfloat162*)(dst + base + 2*K + k)     = l01;
        *(__nv_bfloat162*)(dst + base + 2*K + k + 2) = l23;
    }
}

// ---------------- mma.sync bf16 GEMM (unchanged) ----------------
#define ASTG 16384
#define BSTG 32768
#define STG  (ASTG + BSTG)
#define GEMM_SMEM (4 * STG + 2048)

__global__ __launch_bounds__(256, 1)
void gemm_mma3(const __nv_bfloat16* __restrict__ Ag, const __nv_bfloat16* __restrict__ Bg,
               const float* __restrict__ b1, const float* __restrict__ b2,
               float* __restrict__ C, int Mt, int K3, int Ncols, int GN)
{
    extern __shared__ char smem_raw[];
    const uint32_t sraw = s2u(smem_raw);
    const uint32_t sb0  = (sraw + 1023u) & ~1023u;
    float* sbias = (float*)(smem_raw + (sb0 - sraw) + 4 * STG);

    const int tid  = threadIdx.x;
    const int wid  = tid >> 5;
    const int lane = tid & 31;
    const int NC   = K3 >> 6;

    int gw  = Mt * GN;
    int gid = blockIdx.x / gw;
    int rem = blockIdx.x % gw;
    int m0 = (rem % Mt) * 128;
    int n0 = (gid * GN + rem / Mt) * 256;

    sbias[tid] = b1[n0 + tid] + (b2 ? b2[n0 + tid] : 0.f);

    const int rbase = tid >> 3;
    const int seg   = tid & 7;
    uint32_t swA[4], swB[8];
#pragma unroll
    for (int r = 0; r < 4; r++)
        swA[r] = sw128((uint32_t)(rbase + r * 32) * 128u + (uint32_t)seg * 16u);
#pragma unroll
    for (int r = 0; r < 8; r++)
        swB[r] = sw128((uint32_t)(rbase + r * 32) * 128u + (uint32_t)seg * 16u);
    const __nv_bfloat16* Asrc = Ag + (size_t)(m0 + rbase) * K3 + seg * 8;
    const __nv_bfloat16* Bsrc = Bg + (size_t)(n0 + rbase) * K3 + seg * 8;
    const size_t rstride = (size_t)32 * K3;

    const int wm = wid & 1;
    const int wn = wid >> 1;
    const int arow = wm * 64 + (lane & 15);
    const uint32_t akoff = (uint32_t)(lane >> 4) * 16u;
    const int brow = wn * 64 + ((lane >> 4) & 1) * 8 + (lane & 7);
    const uint32_t bkoff = (uint32_t)((lane >> 3) & 1) * 16u;

    float d[4][8][4];
#pragma unroll
    for (int i = 0; i < 4; i++)
#pragma unroll
        for (int j = 0; j < 8; j++)
#pragma unroll
            for (int q = 0; q < 4; q++) d[i][j][q] = 0.f;

#pragma unroll
    for (int c = 0; c < 3; c++) {
        uint32_t ab = sb0 + c * STG;
        uint32_t bb = ab + ASTG;
#pragma unroll
        for (int r = 0; r < 4; r++)
            cp16(ab + swA[r], Asrc + r * rstride + (size_t)c * 64);
#pragma unroll
        for (int r = 0; r < 8; r++)
            cp16(bb + swB[r], Bsrc + r * rstride + (size_t)c * 64);
        CP_COMMIT();
    }

    for (int c = 0; c < NC; ++c) {
        CP_WAIT2();
        __syncthreads();

        int slot = c & 3;
        uint32_t sA = sb0 + slot * STG;
        uint32_t sB = sA + ASTG;

#pragma unroll
        for (int ks = 0; ks < 4; ks++) {
            uint32_t kb = (uint32_t)ks * 32u;
            uint32_t a[4][4], bq[4][4];
#pragma unroll
            for (int i = 0; i < 4; i++) {
                uint32_t addr = sA + sw128((uint32_t)(arow + 16 * i) * 128u + kb + akoff);
                LDSM_X4(a[i][0], a[i][1], a[i][2], a[i][3], addr);
            }
#pragma unroll
            for (int j = 0; j < 4; j++) {
                uint32_t addr = sB + sw128((uint32_t)(brow + 16 * j) * 128u + kb + bkoff);
                LDSM_X4(bq[j][0], bq[j][1], bq[j][2], bq[j][3], addr);
            }
#pragma unroll
            for (int i = 0; i < 4; i++) {
#pragma unroll
                for (int j = 0; j < 4; j++) {
                    MMA16816(d[i][2 * j],     a[i], bq[j][0], bq[j][1]);
                    MMA16816(d[i][2 * j + 1], a[i], bq[j][2], bq[j][3]);
                }
            }
        }

        int cl = c + 3;
        if (cl < NC) {
            int ls = cl & 3;
            uint32_t ab = sb0 + ls * STG;
            uint32_t bb = ab + ASTG;
#pragma unroll
            for (int r = 0; r < 4; r++)
                cp16(ab + swA[r], Asrc + r * rstride + (size_t)cl * 64);
#pragma unroll
            for (int r = 0; r < 8; r++)
                cp16(bb + swB[r], Bsrc + r * rstride + (size_t)cl * 64);
            CP_COMMIT();
        }
    }

    const int erow = lane >> 2;
    const int ecol = (lane & 3) * 2;
#pragma unroll
    for (int i = 0; i < 4; i++) {
        int r0 = m0 + wm * 64 + i * 16 + erow;
#pragma unroll
        for (int j = 0; j < 8; j++) {
            int cbase = wn * 64 + j * 8 + ecol;
            float bz0 = sbias[cbase], bz1 = sbias[cbase + 1];
            float2 v0 = { d[i][j][0] + bz0, d[i][j][1] + bz1 };
            float2 v1 = { d[i][j][2] + bz0, d[i][j][3] + bz1 };
            *(float2*)(C + (size_t)r0 * Ncols + n0 + cbase)       = v0;
            *(float2*)(C + (size_t)(r0 + 8) * Ncols + n0 + cbase) = v1;
        }
    }
}

// ---------------- persistent LSTM scan v10 ----------------
// R13 structure + (1) per-lane parallel activations before gather,
// (2) bf16x3 h-split fused into the scan, written one step late under the
// h-staging LDG latency, (3) c_out written after the loop.
__global__ __launch_bounds__(256, 1)
void lstm_seq(const float* __restrict__ Whh, const float* __restrict__ xg,
              const float* __restrict__ c0, __nv_bfloat16* __restrict__ a3h_out,
              float* __restrict__ c_out, int T)
{
    __shared__ ulonglong2 sh2[256];   // h_t (1024 floats)
    __shared__ float sp[8][33];       // per-warp partials

    const int tid  = threadIdx.x;
    const int warp = tid >> 5;
    const int lane = tid & 31;
    const int cta  = blockIdx.x;
    const int g    = lane >> 3;       // gate 0..3
    const int jj   = lane & 7;        // local hidden unit
    const int row  = g * HID + cta * 8 + jj;
    const int hidx = cta * 8 + lane;  // unit for finalize lanes (<8)

    ulonglong2 w2[32];
    {
        const ulonglong2* wp =
            (const ulonglong2*)(Whh + (size_t)row * HID + warp * 128);
#pragma unroll
        for (int i = 0; i < 32; i++) w2[i] = wp[i];
    }

    float creg = 0.f;
    if (tid < 8) creg = c0[cta * 8 + tid];
    unsigned* ctr = &g_ctr;

    const float* xgp = xg + (size_t)g * HID + cta * 8 + jj;
    float xgv_next = 0.f;
    if (tid < 32) xgv_next = __ldg(xgp);

    float p_hnew = 0.f;               // pending h for fused bf16x3 write

    for (int t = 0; t < T; ++t) {
        // stage h_t into smem (L1 bypass; sh2 region is warp-private)
        sh2[tid] = __ldcg(((const ulonglong2*)g_hbuf[t & 1]) + tid);
        float xgv = xgv_next;
        if (tid < 32 && t + 1 < T)
            xgv_next = __ldg(xgp + (size_t)(t + 1) * G4);

        // fused bf16x3 write of h_{t} (computed last iter) — hidden under LDG
        if (a3h_out && warp == 0 && lane < 8 && t > 0) {
            __nv_bfloat16 hhi = __float2bfloat16_rn(p_hnew);
            __nv_bfloat16 hlo = __float2bfloat16_rn(p_hnew - __bfloat162float(hhi));
            size_t rb = (size_t)(t - 1) * K3H;
            a3h_out[rb + hidx]           = hhi;
            a3h_out[rb + HID + hidx]     = hlo;
            a3h_out[rb + 2 * HID + hidx] = hhi;
        }
        __syncwarp();                                 // (A') warp-local staging

        // 128-wide dot, packed f32x2, warp-uniform smem reads (broadcast)
        ull a0 = 0, a1 = 0, a2 = 0, a3 = 0;
        const ulonglong2* hp = sh2 + warp * 32;
#pragma unroll
        for (int j = 0; j < 32; j += 2) {
            ulonglong2 ha = hp[j];
            ulonglong2 hb = hp[j + 1];
            FMA2(a0, w2[j].x, ha.x);
            FMA2(a1, w2[j].y, ha.y);
            FMA2(a2, w2[j + 1].x, hb.x);
            FMA2(a3, w2[j + 1].y, hb.y);
        }
        ull t01, t23, tt;
        ADD2(t01, a0, a1);
        ADD2(t23, a2, a3);
        ADD2(tt, t01, t23);
        uint32_t lo, hi;
        asm("mov.b64 {%0, %1}, %2;" : "=r"(lo), "=r"(hi) : "l"(tt));
        sp[warp][lane] = __uint_as_float(lo) + __uint_as_float(hi);
        __syncthreads();                              // (B) partials ready

        if (warp == 0) {
            float s = xgv;
#pragma unroll
            for (int w = 0; w < 8; w++) s += sp[w][lane];
            // parallel per-lane activation (gate 2 = tanh, others = sigmoid)
            float act = (g == 2) ? tanh_apx(s) : sigf(s);
            float ai = __shfl_sync(0xffffffffu, act, lane & 7);
            float af = __shfl_sync(0xffffffffu, act, 8 + (lane & 7));
            float az = __shfl_sync(0xffffffffu, act, 16 + (lane & 7));
            float ao = __shfl_sync(0xffffffffu, act, 24 + (lane & 7));
            if (lane < 8) {
                creg = af * creg + ai * az;
                float hnew = ao * tanh_apx(creg);
                p_hnew = hnew;
                g_hbuf[(t + 1) & 1][hidx] = hnew;
            }
            __syncwarp();
            if (lane == 0) {
                unsigned old;
                asm volatile("atom.acq_rel.gpu.global.add.u32 %0, [%1], 1;"
                             : "=r"(old) : "l"(ctr) : "memory");
                unsigned tgt = (unsigned)(t + 1) * (unsigned)NCTA;
                if (old + 1u != tgt) {
                    unsigned v;
                    do {
                        asm volatile("ld.acquire.gpu.global.u32 %0, [%1];"
                                     : "=r"(v) : "l"(ctr) : "memory");
                    } while (v < tgt);
                }
            }
        }
        __syncthreads();                              // (C) barrier done
    }

    // epilogue: flush pending h_{T-1} and final cell state
    if (warp == 0 && lane < 8) {
        if (a3h_out) {
            __nv_bfloat16 hhi = __float2bfloat16_rn(p_hnew);
            __nv_bfloat16 hlo = __float2bfloat16_rn(p_hnew - __bfloat162float(hhi));
            size_t rb = (size_t)(T - 1) * K3H;
            a3h_out[rb + hidx]           = hhi;
            a3h_out[rb + HID + hidx]     = hlo;
            a3h_out[rb + 2 * HID + hidx] = hhi;
        }
        if (c_out) c_out[hidx] = creg;
    }
}

// ---------------- launch ----------------
static void launch_gemm(const __nv_bfloat16* A, const __nv_bfloat16* B,
                        const float* b1, const float* b2, float* C,
                        int M, int N, int K3, int GN)
{
    int Mt = M / 128, Nt = N / 256;
    cudaFuncSetAttribute(gemm_mma3, cudaFuncAttributeMaxDynamicSharedMemorySize, GEMM_SMEM);
    gemm_mma3<<<Mt * Nt, 256, GEMM_SMEM>>>(A, B, b1, b2, C, Mt, K3, N, GN);
}

extern "C" void kernel_launch(void* const* d_in, const int* in_sizes, int n_in,
                              void* d_out, int out_size)
{
    const int*   e1       = (const int*)d_in[0];
    const int*   gt       = (const int*)d_in[1];
    const float* emb_i    = (const float*)d_in[2];
    const float* emb_o    = (const float*)d_in[3];
    const float* enc_Wih  = (const float*)d_in[4];
    const float* enc_Whh  = (const float*)d_in[5];
    const float* enc_bih  = (const float*)d_in[6];
    const float* enc_bhh  = (const float*)d_in[7];
    const float* dec_Wih  = (const float*)d_in[8];
    const float* dec_Whh  = (const float*)d_in[9];
    const float* dec_bih  = (const float*)d_in[10];
    const float* dec_bhh  = (const float*)d_in[11];
    const float* outW     = (const float*)d_in[12];
    const float* outb     = (const float*)d_in[13];
    float*       out      = (float*)d_out;

    float *xge, *xgd, *cenc, *czero;
    int* didx;
    __nv_bfloat16 *a3e, *a3d, *w3e, *w3d, *b3o, *a3h;
    cudaGetSymbolAddress((void**)&xge,   g_xg_enc);
    cudaGetSymbolAddress((void**)&xgd,   g_xg_dec);
    cudaGetSymbolAddress((void**)&cenc,  g_cenc);
    cudaGetSymbolAddress((void**)&czero, g_czero);
    cudaGetSymbolAddress((void**)&didx,  g_decidx);
    cudaGetSymbolAddress((void**)&a3e,   g_A3e);
    cudaGetSymbolAddress((void**)&a3d,   g_A3d);
    cudaGetSymbolAddress((void**)&w3e,   g_W3e);
    cudaGetSymbolAddress((void**)&w3d,   g_W3d);
    cudaGetSymbolAddress((void**)&b3o,   g_B3o);
    cudaGetSymbolAddress((void**)&a3h,   g_A3h);

    init0_kernel<<<8, 256>>>(gt);

    // bf16x3 conversions
    {
        long t1 = (long)G4 * EMB;
        conv_split<<<(int)(t1 / 4 / 256), 256>>>(enc_Wih, nullptr, w3e, EMB, t1, 1);
        conv_split<<<(int)(t1 / 4 / 256), 256>>>(dec_Wih, nullptr, w3d, EMB, t1, 1);
        long t2 = (long)OSIZE * HID;
        conv_split<<<(int)(t2 / 4 / 256), 256>>>(outW, nullptr, b3o, HID, t2, 1);
        long t3 = (long)TLEN * EMB;
        conv_split<<<(int)(t3 / 4 / 256), 256>>>(emb_i, e1,   a3e, EMB, t3, 0);
        conv_split<<<(int)(t3 / 4 / 256), 256>>>(emb_o, didx, a3d, EMB, t3, 0);
    }

    // x-gates
    launch_gemm(a3e, w3e, enc_bih, enc_bhh, xge, TLEN, G4, K3E, 16);
    launch_gemm(a3d, w3d, dec_bih, dec_bhh, xgd, TLEN, G4, K3E, 16);

    // encoder scan (keeps final cell state)
    lstm_seq<<<NCTA, 256>>>(enc_Whh, xge, czero, nullptr, cenc, TLEN);
    init1_kernel<<<4, 256>>>();
    // decoder scan — writes bf16x3 h panel directly
    lstm_seq<<<NCTA, 256>>>(dec_Whh, xgd, cenc, a3h, nullptr, TLEN);

    // logits
    launch_gemm(a3h, b3o, outb, nullptr, out, TLEN, OSIZE, K3H, 25);
}

// round 15
// speedup vs baseline: 1.4101x; 1.0308x over previous
#include <cuda_runtime.h>
#include <cuda_bf16.h>
#include <math.h>
#include <stdint.h>

#define HID   1024
#define EMB   512
#define TLEN  2048
#define G4    4096
#define NCTA  128
#define OSIZE 32000
#define K3E   (3*EMB)
#define K3H   (3*HID)
#define NREP  8

typedef unsigned long long ull;

// ---------------- scratch ----------------
__device__ float g_xg_enc[(size_t)TLEN * G4];
__device__ float g_xg_dec[(size_t)TLEN * G4];
__device__ float g_hrep[2][NREP][HID];   // parity x replica x unit
__device__ float g_cenc[HID];
__device__ float g_czero[HID];
__device__ int   g_decidx[TLEN];
__device__ unsigned g_ctr;
__device__ __nv_bfloat16 g_A3e[(size_t)TLEN * K3E];
__device__ __nv_bfloat16 g_A3d[(size_t)TLEN * K3E];
__device__ __nv_bfloat16 g_W3e[(size_t)G4 * K3E];
__device__ __nv_bfloat16 g_W3d[(size_t)G4 * K3E];
__device__ __nv_bfloat16 g_B3o[(size_t)OSIZE * K3H];
__device__ __nv_bfloat16 g_A3h[(size_t)TLEN * K3H];

// ---------------- helpers ----------------
__device__ __forceinline__ uint32_t s2u(const void* p) {
    return (uint32_t)__cvta_generic_to_shared(p);
}
__device__ __forceinline__ void cp16(uint32_t dst, const void* src) {
    asm volatile("cp.async.cg.shared.global [%0], [%1], 16;" :: "r"(dst), "l"(src) : "memory");
}
#define CP_COMMIT() asm volatile("cp.async.commit_group;" ::: "memory")
#define CP_WAIT2()  asm volatile("cp.async.wait_group 2;" ::: "memory")

#define LDSM_X4(r0, r1, r2, r3, addr) \
    asm volatile("ldmatrix.sync.aligned.m8n8.x4.shared.b16 {%0,%1,%2,%3}, [%4];" \
                 : "=r"(r0), "=r"(r1), "=r"(r2), "=r"(r3) : "r"(addr))

#define MMA16816(d, a, b0, b1) \
    asm volatile("mma.sync.aligned.m16n8k16.row.col.f32.bf16.bf16.f32 " \
                 "{%0,%1,%2,%3}, {%4,%5,%6,%7}, {%8,%9}, {%0,%1,%2,%3};" \
                 : "+f"((d)[0]), "+f"((d)[1]), "+f"((d)[2]), "+f"((d)[3]) \
                 : "r"((a)[0]), "r"((a)[1]), "r"((a)[2]), "r"((a)[3]), \
                   "r"(b0), "r"(b1))

#define FMA2(acc, w, h) \
    asm("fma.rn.f32x2 %0, %1, %2, %0;" : "+l"(acc) : "l"(w), "l"(h))
#define ADD2(d, a, b) \
    asm("add.rn.f32x2 %0, %1, %2;" : "=l"(d) : "l"(a), "l"(b))

__device__ __forceinline__ float tanh_apx(float x) {
    float r;
    asm("tanh.approx.f32 %0, %1;" : "=f"(r) : "f"(x));
    return r;
}
__device__ __forceinline__ float sigf(float x) {
    return fmaf(tanh_apx(0.5f * x), 0.5f, 0.5f);
}

static __device__ __forceinline__ uint32_t sw128(uint32_t off) {
    return off ^ ((off >> 3) & 0x70);
}

// ---------------- init kernels ----------------
__global__ void init0_kernel(const int* __restrict__ gt) {
    int i = blockIdx.x * blockDim.x + threadIdx.x;
    if (i == 0) g_ctr = 0u;
    if (i < HID) {
        g_czero[i] = 0.f;
#pragma unroll
        for (int r = 0; r < NREP; r++) {
            g_hrep[0][r][i] = 0.f;
            g_hrep[1][r][i] = 0.f;
        }
    }
    if (i < TLEN) g_decidx[i] = (i == 0) ? 1 : gt[i - 1];
}
__global__ void init1_kernel() {
    int i = blockIdx.x * blockDim.x + threadIdx.x;
    if (i == 0) g_ctr = 0u;
    if (i < HID) {
        float v = g_cenc[i];
#pragma unroll
        for (int r = 0; r < NREP; r++) g_hrep[0][r][i] = v;
    }
}

// ---------------- bf16 hi/lo split: mode 0 => [hi|lo|hi], mode 1 => [hi|hi|lo] ----------------
__global__ __launch_bounds__(256)
void conv_split(const float* __restrict__ src, const int* __restrict__ idx,
                __nv_bfloat16* __restrict__ dst, int K, long total, int mode)
{
    long i = ((long)blockIdx.x * blockDim.x + threadIdx.x) * 4;
    if (i >= total) return;
    int r = (int)(i / K);
    int k = (int)(i % K);
    int srow = idx ? idx[r] : r;
    float4 v = *(const float4*)(src + (size_t)srow * K + k);

    __nv_bfloat16 hx = __float2bfloat16_rn(v.x), hy = __float2bfloat16_rn(v.y);
    __nv_bfloat16 hz = __float2bfloat16_rn(v.z), hw = __float2bfloat16_rn(v.w);
    __nv_bfloat16 lx = __float2bfloat16_rn(v.x - __bfloat162float(hx));
    __nv_bfloat16 ly = __float2bfloat16_rn(v.y - __bfloat162float(hy));
    __nv_bfloat16 lz = __float2bfloat16_rn(v.z - __bfloat162float(hz));
    __nv_bfloat16 lw = __float2bfloat16_rn(v.w - __bfloat162float(hw));

    size_t base = (size_t)r * 3 * K;
    __nv_bfloat162 h01 = {hx, hy}, h23 = {hz, hw};
    __nv_bfloat162 l01 = {lx, ly}, l23 = {lz, lw};

    *(__nv_bfloat162*)(dst + base + k)     = h01;
    *(__nv_bfloat162*)(dst + base + k + 2) = h23;
    if (mode == 0) {
        *(__nv_bfloat162*)(dst + base + K + k)       = l01;
        *(__nv_bfloat162*)(dst + base + K + k + 2)   = l23;
        *(__nv_bfloat162*)(dst + base + 2*K + k)     = h01;
        *(__nv_bfloat162*)(dst + base + 2*K + k + 2) = h23;
    } else {
        *(__nv_bfloat162*)(dst + base + K + k)       = h01;
        *(__nv_bfloat162*)(dst + base + K + k + 2)   = h23;
        *(__nv_bfloat162*)(dst + base + 2*K + k)     = l01;
        *(__nv_bfloat162*)(dst + base + 2*K + k + 2) = l23;
    }
}

// ---------------- mma.sync bf16 GEMM (unchanged) ----------------
#define ASTG 16384
#define BSTG 32768
#define STG  (ASTG + BSTG)
#define GEMM_SMEM (4 * STG + 2048)

__global__ __launch_bounds__(256, 1)
void gemm_mma3(const __nv_bfloat16* __restrict__ Ag, const __nv_bfloat16* __restrict__ Bg,
               const float* __restrict__ b1, const float* __restrict__ b2,
               float* __restrict__ C, int Mt, int K3, int Ncols, int GN)
{
    extern __shared__ char smem_raw[];
    const uint32_t sraw = s2u(smem_raw);
    const uint32_t sb0  = (sraw + 1023u) & ~1023u;
    float* sbias = (float*)(smem_raw + (sb0 - sraw) + 4 * STG);

    const int tid  = threadIdx.x;
    const int wid  = tid >> 5;
    const int lane = tid & 31;
    const int NC   = K3 >> 6;

    int gw  = Mt * GN;
    int gid = blockIdx.x / gw;
    int rem = blockIdx.x % gw;
    int m0 = (rem % Mt) * 128;
    int n0 = (gid * GN + rem / Mt) * 256;

    sbias[tid] = b1[n0 + tid] + (b2 ? b2[n0 + tid] : 0.f);

    const int rbase = tid >> 3;
    const int seg   = tid & 7;
    uint32_t swA[4], swB[8];
#pragma unroll
    for (int r = 0; r < 4; r++)
        swA[r] = sw128((uint32_t)(rbase + r * 32) * 128u + (uint32_t)seg * 16u);
#pragma unroll
    for (int r = 0; r < 8; r++)
        swB[r] = sw128((uint32_t)(rbase + r * 32) * 128u + (uint32_t)seg * 16u);
    const __nv_bfloat16* Asrc = Ag + (size_t)(m0 + rbase) * K3 + seg * 8;
    const __nv_bfloat16* Bsrc = Bg + (size_t)(n0 + rbase) * K3 + seg * 8;
    const size_t rstride = (size_t)32 * K3;

    const int wm = wid & 1;
    const int wn = wid >> 1;
    const int arow = wm * 64 + (lane & 15);
    const uint32_t akoff = (uint32_t)(lane >> 4) * 16u;
    const int brow = wn * 64 + ((lane >> 4) & 1) * 8 + (lane & 7);
    const uint32_t bkoff = (uint32_t)((lane >> 3) & 1) * 16u;

    float d[4][8][4];
#pragma unroll
    for (int i = 0; i < 4; i++)
#pragma unroll
        for (int j = 0; j < 8; j++)
#pragma unroll
            for (int q = 0; q < 4; q++) d[i][j][q] = 0.f;

#pragma unroll
    for (int c = 0; c < 3; c++) {
        uint32_t ab = sb0 + c * STG;
        uint32_t bb = ab + ASTG;
#pragma unroll
        for (int r = 0; r < 4; r++)
            cp16(ab + swA[r], Asrc + r * rstride + (size_t)c * 64);
#pragma unroll
        for (int r = 0; r < 8; r++)
            cp16(bb + swB[r], Bsrc + r * rstride + (size_t)c * 64);
        CP_COMMIT();
    }

    for (int c = 0; c < NC; ++c) {
        CP_WAIT2();
        __syncthreads();

        int slot = c & 3;
        uint32_t sA = sb0 + slot * STG;
        uint32_t sB = sA + ASTG;

#pragma unroll
        for (int ks = 0; ks < 4; ks++) {
            uint32_t kb = (uint32_t)ks * 32u;
            uint32_t a[4][4], bq[4][4];
#pragma unroll
            for (int i = 0; i < 4; i++) {
                uint32_t addr = sA + sw128((uint32_t)(arow + 16 * i) * 128u + kb + akoff);
                LDSM_X4(a[i][0], a[i][1], a[i][2], a[i][3], addr);
            }
#pragma unroll
            for (int j = 0; j < 4; j++) {
                uint32_t addr = sB + sw128((uint32_t)(brow + 16 * j) * 128u + kb + bkoff);
                LDSM_X4(bq[j][0], bq[j][1], bq[j][2], bq[j][3], addr);
            }
#pragma unroll
            for (int i = 0; i < 4; i++) {
#pragma unroll
                for (int j = 0; j < 4; j++) {
                    MMA16816(d[i][2 * j],     a[i], bq[j][0], bq[j][1]);
                    MMA16816(d[i][2 * j + 1], a[i], bq[j][2], bq[j][3]);
                }
            }
        }

        int cl = c + 3;
        if (cl < NC) {
            int ls = cl & 3;
            uint32_t ab = sb0 + ls * STG;
            uint32_t bb = ab + ASTG;
#pragma unroll
            for (int r = 0; r < 4; r++)
                cp16(ab + swA[r], Asrc + r * rstride + (size_t)cl * 64);
#pragma unroll
            for (int r = 0; r < 8; r++)
                cp16(bb + swB[r], Bsrc + r * rstride + (size_t)cl * 64);
            CP_COMMIT();
        }
    }

    const int erow = lane >> 2;
    const int ecol = (lane & 3) * 2;
#pragma unroll
    for (int i = 0; i < 4; i++) {
        int r0 = m0 + wm * 64 + i * 16 + erow;
#pragma unroll
        for (int j = 0; j < 8; j++) {
            int cbase = wn * 64 + j * 8 + ecol;
            float bz0 = sbias[cbase], bz1 = sbias[cbase + 1];
            float2 v0 = { d[i][j][0] + bz0, d[i][j][1] + bz1 };
            float2 v1 = { d[i][j][2] + bz0, d[i][j][3] + bz1 };
            *(float2*)(C + (size_t)r0 * Ncols + n0 + cbase)       = v0;
            *(float2*)(C + (size_t)(r0 + 8) * Ncols + n0 + cbase) = v1;
        }
    }
}

// ---------------- persistent LSTM scan v11 ----------------
// R14 structure + 8-way h replication: warp0 keeps creg on ALL lanes
// (each 8-lane group redundantly finalizes its unit), and the 32 lanes
// publish h to 8 replicas (2 STG/lane, 4KB apart -> different LTS slices).
// Consumer CTA i stages from replica (i & 7), cutting per-slice L2 read
// serialization of the h broadcast by 8x.
__global__ __launch_bounds__(256, 1)
void lstm_seq(const float* __restrict__ Whh, const float* __restrict__ xg,
              const float* __restrict__ c0, __nv_bfloat16* __restrict__ a3h_out,
              float* __restrict__ c_out, int T)
{
    __shared__ ulonglong2 sh2[256];   // h_t (1024 floats)
    __shared__ float sp[8][33];       // per-warp partials

    const int tid  = threadIdx.x;
    const int warp = tid >> 5;
    const int lane = tid & 31;
    const int cta  = blockIdx.x;
    const int g    = lane >> 3;       // gate 0..3
    const int jj   = lane & 7;        // local hidden unit
    const int row  = g * HID + cta * 8 + jj;
    const int u8   = cta * 8 + (lane & 7);   // unit for finalize groups
    const int rep0 = lane >> 3;              // replica 0..3 (then +4)

    ulonglong2 w2[32];
    {
        const ulonglong2* wp =
            (const ulonglong2*)(Whh + (size_t)row * HID + warp * 128);
#pragma unroll
        for (int i = 0; i < 32; i++) w2[i] = wp[i];
    }

    float creg = 0.f;
    if (warp == 0) creg = c0[u8];     // all 32 lanes (replicated per 8-group)
    unsigned* ctr = &g_ctr;

    const float* xgp = xg + (size_t)g * HID + cta * 8 + jj;
    float xgv_next = 0.f;
    if (tid < 32) xgv_next = __ldg(xgp);

    // consumer reads replica (cta & 7)
    const ulonglong2* hsrc0 = ((const ulonglong2*)g_hrep[0][cta & 7]) + tid;
    const ulonglong2* hsrc1 = ((const ulonglong2*)g_hrep[1][cta & 7]) + tid;

    float p_hnew = 0.f;

    for (int t = 0; t < T; ++t) {
        // stage h_t into smem (L1 bypass; sh2 region is warp-private)
        sh2[tid] = __ldcg((t & 1) ? hsrc1 : hsrc0);
        float xgv = xgv_next;
        if (tid < 32 && t + 1 < T)
            xgv_next = __ldg(xgp + (size_t)(t + 1) * G4);

        // fused bf16x3 write of h (from last iter) — hidden under LDG
        if (a3h_out && warp == 0 && lane < 8 && t > 0) {
            __nv_bfloat16 hhi = __float2bfloat16_rn(p_hnew);
            __nv_bfloat16 hlo = __float2bfloat16_rn(p_hnew - __bfloat162float(hhi));
            size_t rb = (size_t)(t - 1) * K3H;
            a3h_out[rb + u8]           = hhi;
            a3h_out[rb + HID + u8]     = hlo;
            a3h_out[rb + 2 * HID + u8] = hhi;
        }
        __syncwarp();                                 // (A') warp-local staging

        // 128-wide dot, packed f32x2, warp-uniform smem reads (broadcast)
        ull a0 = 0, a1 = 0, a2 = 0, a3 = 0;
        const ulonglong2* hp = sh2 + warp * 32;
#pragma unroll
        for (int j = 0; j < 32; j += 2) {
            ulonglong2 ha = hp[j];
            ulonglong2 hb = hp[j + 1];
            FMA2(a0, w2[j].x, ha.x);
            FMA2(a1, w2[j].y, ha.y);
            FMA2(a2, w2[j + 1].x, hb.x);
            FMA2(a3, w2[j + 1].y, hb.y);
        }
        ull t01, t23, tt;
        ADD2(t01, a0, a1);
        ADD2(t23, a2, a3);
        ADD2(tt, t01, t23);
        uint32_t lo, hi;
        asm("mov.b64 {%0, %1}, %2;" : "=r"(lo), "=r"(hi) : "l"(tt));
        sp[warp][lane] = __uint_as_float(lo) + __uint_as_float(hi);
        __syncthreads();                              // (B) partials ready

        if (warp == 0) {
            float s = xgv;
#pragma unroll
            for (int w = 0; w < 8; w++) s += sp[w][lane];
            float act = (g == 2) ? tanh_apx(s) : sigf(s);
            float ai = __shfl_sync(0xffffffffu, act, lane & 7);
            float af = __shfl_sync(0xffffffffu, act, 8 + (lane & 7));
            float az = __shfl_sync(0xffffffffu, act, 16 + (lane & 7));
            float ao = __shfl_sync(0xffffffffu, act, 24 + (lane & 7));

            // all 32 lanes finalize unit u8 redundantly (identical math)
            creg = af * creg + ai * az;
            float hnew = ao * tanh_apx(creg);
            p_hnew = hnew;

            // publish to 8 replicas: lane -> replica rep0 and rep0+4
            float* outb = &g_hrep[(t + 1) & 1][0][0];
            outb[(size_t)rep0 * HID + u8]       = hnew;
            outb[(size_t)(rep0 + 4) * HID + u8] = hnew;

            __syncwarp();
            if (lane == 0) {
                unsigned old;
                asm volatile("atom.acq_rel.gpu.global.add.u32 %0, [%1], 1;"
                             : "=r"(old) : "l"(ctr) : "memory");
                unsigned tgt = (unsigned)(t + 1) * (unsigned)NCTA;
                if (old + 1u != tgt) {
                    unsigned v;
                    do {
                        asm volatile("ld.acquire.gpu.global.u32 %0, [%1];"
                                     : "=r"(v) : "l"(ctr) : "memory");
                    } while (v < tgt);
                }
            }
        }
        __syncthreads();                              // (C) barrier done
    }

    // epilogue: flush pending h_{T-1} and final cell state
    if (warp == 0 && lane < 8) {
        if (a3h_out) {
            __nv_bfloat16 hhi = __float2bfloat16_rn(p_hnew);
            __nv_bfloat16 hlo = __float2bfloat16_rn(p_hnew - __bfloat162float(hhi));
            size_t rb = (size_t)(T - 1) * K3H;
            a3h_out[rb + u8]           = hhi;
            a3h_out[rb + HID + u8]     = hlo;
            a3h_out[rb + 2 * HID + u8] = hhi;
        }
        if (c_out) c_out[u8] = creg;
    }
}

// ---------------- launch ----------------
static void launch_gemm(const __nv_bfloat16* A, const __nv_bfloat16* B,
                        const float* b1, const float* b2, float* C,
                        int M, int N, int K3, int GN)
{
    int Mt = M / 128, Nt = N / 256;
    cudaFuncSetAttribute(gemm_mma3, cudaFuncAttributeMaxDynamicSharedMemorySize, GEMM_SMEM);
    gemm_mma3<<<Mt * Nt, 256, GEMM_SMEM>>>(A, B, b1, b2, C, Mt, K3, N, GN);
}

extern "C" void kernel_launch(void* const* d_in, const int* in_sizes, int n_in,
                              void* d_out, int out_size)
{
    const int*   e1       = (const int*)d_in[0];
    const int*   gt       = (const int*)d_in[1];
    const float* emb_i    = (const float*)d_in[2];
    const float* emb_o    = (const float*)d_in[3];
    const float* enc_Wih  = (const float*)d_in[4];
    const float* enc_Whh  = (const float*)d_in[5];
    const float* enc_bih  = (const float*)d_in[6];
    const float* enc_bhh  = (const float*)d_in[7];
    const float* dec_Wih  = (const float*)d_in[8];
    const float* dec_Whh  = (const float*)d_in[9];
    const float* dec_bih  = (const float*)d_in[10];
    const float* dec_bhh  = (const float*)d_in[11];
    const float* outW     = (const float*)d_in[12];
    const float* outb     = (const float*)d_in[13];
    float*       out      = (float*)d_out;

    float *xge, *xgd, *cenc, *czero;
    int* didx;
    __nv_bfloat16 *a3e, *a3d, *w3e, *w3d, *b3o, *a3h;
    cudaGetSymbolAddress((void**)&xge,   g_xg_enc);
    cudaGetSymbolAddress((void**)&xgd,   g_xg_dec);
    cudaGetSymbolAddress((void**)&cenc,  g_cenc);
    cudaGetSymbolAddress((void**)&czero, g_czero);
    cudaGetSymbolAddress((void**)&didx,  g_decidx);
    cudaGetSymbolAddress((void**)&a3e,   g_A3e);
    cudaGetSymbolAddress((void**)&a3d,   g_A3d);
    cudaGetSymbolAddress((void**)&w3e,   g_W3e);
    cudaGetSymbolAddress((void**)&w3d,   g_W3d);
    cudaGetSymbolAddress((void**)&b3o,   g_B3o);
    cudaGetSymbolAddress((void**)&a3h,   g_A3h);

    init0_kernel<<<8, 256>>>(gt);

    // bf16x3 conversions
    {
        long t1 = (long)G4 * EMB;
        conv_split<<<(int)(t1 / 4 / 256), 256>>>(enc_Wih, nullptr, w3e, EMB, t1, 1);
        conv_split<<<(int)(t1 / 4 / 256), 256>>>(dec_Wih, nullptr, w3d, EMB, t1, 1);
        long t2 = (long)OSIZE * HID;
        conv_split<<<(int)(t2 / 4 / 256), 256>>>(outW, nullptr, b3o, HID, t2, 1);
        long t3 = (long)TLEN * EMB;
        conv_split<<<(int)(t3 / 4 / 256), 256>>>(emb_i, e1,   a3e, EMB, t3, 0);
        conv_split<<<(int)(t3 / 4 / 256), 256>>>(emb_o, didx, a3d, EMB, t3, 0);
    }

    // x-gates
    launch_gemm(a3e, w3e, enc_bih, enc_bhh, xge, TLEN, G4, K3E, 16);
    launch_gemm(a3d, w3d, dec_bih, dec_bhh, xgd, TLEN, G4, K3E, 16);

    // encoder scan (keeps final cell state)
    lstm_seq<<<NCTA, 256>>>(enc_Whh, xge, czero, nullptr, cenc, TLEN);
    init1_kernel<<<4, 256>>>();
    // decoder scan — writes bf16x3 h panel directly
    lstm_seq<<<NCTA, 256>>>(dec_Whh, xgd, cenc, a3h, nullptr, TLEN);

    // logits
    launch_gemm(a3h, b3o, outb, nullptr, out, TLEN, OSIZE, K3H, 25);
}

// round 16
// speedup vs baseline: 1.4547x; 1.0316x over previous
#include <cuda_runtime.h>
#include <cuda_bf16.h>
#include <cuda_fp16.h>
#include <math.h>
#include <stdint.h>

#define HID   1024
#define EMB   512
#define TLEN  2048
#define G4    4096
#define NCTA  128
#define OSIZE 32000
#define K3E   (3*EMB)
#define K2H   (2*HID)
#define NREP  8

typedef unsigned long long ull;

// ---------------- scratch ----------------
__device__ float g_xg_enc[(size_t)TLEN * G4];
__device__ float g_xg_dec[(size_t)TLEN * G4];
__device__ float g_hrep[2][NREP][HID];
__device__ float g_cenc[HID];
__device__ float g_czero[HID];
__device__ int   g_decidx[TLEN];
__device__ unsigned g_ctr;
__device__ __nv_bfloat16 g_A3e[(size_t)TLEN * K3E];
__device__ __nv_bfloat16 g_A3d[(size_t)TLEN * K3E];
__device__ __nv_bfloat16 g_W3e[(size_t)G4 * K3E];
__device__ __nv_bfloat16 g_W3d[(size_t)G4 * K3E];
__device__ __half g_B2o[(size_t)OSIZE * K2H];   // 131 MB fp16 [bh|bh]
__device__ __half g_A2h[(size_t)TLEN * K2H];    // hs [hi|lo] fp16

// ---------------- helpers ----------------
__device__ __forceinline__ uint32_t s2u(const void* p) {
    return (uint32_t)__cvta_generic_to_shared(p);
}
__device__ __forceinline__ void cp16(uint32_t dst, const void* src) {
    asm volatile("cp.async.cg.shared.global [%0], [%1], 16;" :: "r"(dst), "l"(src) : "memory");
}
#define CP_COMMIT() asm volatile("cp.async.commit_group;" ::: "memory")
#define CP_WAIT2()  asm volatile("cp.async.wait_group 2;" ::: "memory")

#define LDSM_X4(r0, r1, r2, r3, addr) \
    asm volatile("ldmatrix.sync.aligned.m8n8.x4.shared.b16 {%0,%1,%2,%3}, [%4];" \
                 : "=r"(r0), "=r"(r1), "=r"(r2), "=r"(r3) : "r"(addr))

#define MMA_BF16(d, a, b0, b1) \
    asm volatile("mma.sync.aligned.m16n8k16.row.col.f32.bf16.bf16.f32 " \
                 "{%0,%1,%2,%3}, {%4,%5,%6,%7}, {%8,%9}, {%0,%1,%2,%3};" \
                 : "+f"((d)[0]), "+f"((d)[1]), "+f"((d)[2]), "+f"((d)[3]) \
                 : "r"((a)[0]), "r"((a)[1]), "r"((a)[2]), "r"((a)[3]), \
                   "r"(b0), "r"(b1))

#define MMA_F16(d, a, b0, b1) \
    asm volatile("mma.sync.aligned.m16n8k16.row.col.f32.f16.f16.f32 " \
                 "{%0,%1,%2,%3}, {%4,%5,%6,%7}, {%8,%9}, {%0,%1,%2,%3};" \
                 : "+f"((d)[0]), "+f"((d)[1]), "+f"((d)[2]), "+f"((d)[3]) \
                 : "r"((a)[0]), "r"((a)[1]), "r"((a)[2]), "r"((a)[3]), \
                   "r"(b0), "r"(b1))

#define FMA2(acc, w, h) \
    asm("fma.rn.f32x2 %0, %1, %2, %0;" : "+l"(acc) : "l"(w), "l"(h))
#define ADD2(d, a, b) \
    asm("add.rn.f32x2 %0, %1, %2;" : "=l"(d) : "l"(a), "l"(b))

__device__ __forceinline__ float tanh_apx(float x) {
    float r;
    asm("tanh.approx.f32 %0, %1;" : "=f"(r) : "f"(x));
    return r;
}
__device__ __forceinline__ float sigf(float x) {
    return fmaf(tanh_apx(0.5f * x), 0.5f, 0.5f);
}

static __device__ __forceinline__ uint32_t sw128(uint32_t off) {
    return off ^ ((off >> 3) & 0x70);
}

// ---------------- init kernels ----------------
__global__ void init0_kernel(const int* __restrict__ gt) {
    int i = blockIdx.x * blockDim.x + threadIdx.x;
    if (i == 0) g_ctr = 0u;
    if (i < HID) {
        g_czero[i] = 0.f;
#pragma unroll
        for (int r = 0; r < NREP; r++) {
            g_hrep[0][r][i] = 0.f;
            g_hrep[1][r][i] = 0.f;
        }
    }
    if (i < TLEN) g_decidx[i] = (i == 0) ? 1 : gt[i - 1];
}
__global__ void init1_kernel() {
    int i = blockIdx.x * blockDim.x + threadIdx.x;
    if (i == 0) g_ctr = 0u;
    if (i < HID) {
        float v = g_cenc[i];
#pragma unroll
        for (int r = 0; r < NREP; r++) g_hrep[0][r][i] = v;
    }
}

// ---------------- bf16 hi/lo split (x-gate paths): mode 0 => [hi|lo|hi], 1 => [hi|hi|lo] ----------------
__global__ __launch_bounds__(256)
void conv_split(const float* __restrict__ src, const int* __restrict__ idx,
                __nv_bfloat16* __restrict__ dst, int K, long total, int mode)
{
    long i = ((long)blockIdx.x * blockDim.x + threadIdx.x) * 4;
    if (i >= total) return;
    int r = (int)(i / K);
    int k = (int)(i % K);
    int srow = idx ? idx[r] : r;
    float4 v = *(const float4*)(src + (size_t)srow * K + k);

    __nv_bfloat16 hx = __float2bfloat16_rn(v.x), hy = __float2bfloat16_rn(v.y);
    __nv_bfloat16 hz = __float2bfloat16_rn(v.z), hw = __float2bfloat16_rn(v.w);
    __nv_bfloat16 lx = __float2bfloat16_rn(v.x - __bfloat162float(hx));
    __nv_bfloat16 ly = __float2bfloat16_rn(v.y - __bfloat162float(hy));
    __nv_bfloat16 lz = __float2bfloat16_rn(v.z - __bfloat162float(hz));
    __nv_bfloat16 lw = __float2bfloat16_rn(v.w - __bfloat162float(hw));

    size_t base = (size_t)r * 3 * K;
    __nv_bfloat162 h01 = {hx, hy}, h23 = {hz, hw};
    __nv_bfloat162 l01 = {lx, ly}, l23 = {lz, lw};

    *(__nv_bfloat162*)(dst + base + k)     = h01;
    *(__nv_bfloat162*)(dst + base + k + 2) = h23;
    if (mode == 0) {
        *(__nv_bfloat162*)(dst + base + K + k)       = l01;
        *(__nv_bfloat162*)(dst + base + K + k + 2)   = l23;
        *(__nv_bfloat162*)(dst + base + 2*K + k)     = h01;
        *(__nv_bfloat162*)(dst + base + 2*K + k + 2) = h23;
    } else {
        *(__nv_bfloat162*)(dst + base + K + k)       = h01;
        *(__nv_bfloat162*)(dst + base + K + k + 2)   = h23;
        *(__nv_bfloat162*)(dst + base + 2*K + k)     = l01;
        *(__nv_bfloat162*)(dst + base + 2*K + k + 2) = l23;
    }
}

// ---------------- fp16 duplicate conversion (outW): dst row = [bh | bh] ----------------
__global__ __launch_bounds__(256)
void conv_dup_f16(const float* __restrict__ src, __half* __restrict__ dst,
                  int K, long total)
{
    long i = ((long)blockIdx.x * blockDim.x + threadIdx.x) * 4;
    if (i >= total) return;
    int r = (int)(i / K);
    int k = (int)(i % K);
    float4 v = *(const float4*)(src + (size_t)r * K + k);
    __half2 h01 = {__float2half_rn(v.x), __float2half_rn(v.y)};
    __half2 h23 = {__float2half_rn(v.z), __float2half_rn(v.w)};
    size_t base = (size_t)r * 2 * K;
    *(__half2*)(dst + base + k)         = h01;
    *(__half2*)(dst + base + k + 2)     = h23;
    *(__half2*)(dst + base + K + k)     = h01;
    *(__half2*)(dst + base + K + k + 2) = h23;
}

// ---------------- mma.sync GEMM (dtype-templated): C[M,N]=A[M,K]*B[N,K]^T + bias ----------------
#define ASTG 16384
#define BSTG 32768
#define STG  (ASTG + BSTG)
#define GEMM_SMEM (4 * STG + 2048)

template<bool F16>
__global__ __launch_bounds__(256, 1)
void gemm_mma3(const __nv_bfloat16* __restrict__ Ag, const __nv_bfloat16* __restrict__ Bg,
               const float* __restrict__ b1, const float* __restrict__ b2,
               float* __restrict__ C, int Mt, int K3, int Ncols, int GN)
{
    extern __shared__ char smem_raw[];
    const uint32_t sraw = s2u(smem_raw);
    const uint32_t sb0  = (sraw + 1023u) & ~1023u;
    float* sbias = (float*)(smem_raw + (sb0 - sraw) + 4 * STG);

    const int tid  = threadIdx.x;
    const int wid  = tid >> 5;
    const int lane = tid & 31;
    const int NC   = K3 >> 6;

    int gw  = Mt * GN;
    int gid = blockIdx.x / gw;
    int rem = blockIdx.x % gw;
    int m0 = (rem % Mt) * 128;
    int n0 = (gid * GN + rem / Mt) * 256;

    sbias[tid] = b1[n0 + tid] + (b2 ? b2[n0 + tid] : 0.f);

    const int rbase = tid >> 3;
    const int seg   = tid & 7;
    uint32_t swA[4], swB[8];
#pragma unroll
    for (int r = 0; r < 4; r++)
        swA[r] = sw128((uint32_t)(rbase + r * 32) * 128u + (uint32_t)seg * 16u);
#pragma unroll
    for (int r = 0; r < 8; r++)
        swB[r] = sw128((uint32_t)(rbase + r * 32) * 128u + (uint32_t)seg * 16u);
    const __nv_bfloat16* Asrc = Ag + (size_t)(m0 + rbase) * K3 + seg * 8;
    const __nv_bfloat16* Bsrc = Bg + (size_t)(n0 + rbase) * K3 + seg * 8;
    const size_t rstride = (size_t)32 * K3;

    const int wm = wid & 1;
    const int wn = wid >> 1;
    const int arow = wm * 64 + (lane & 15);
    const uint32_t akoff = (uint32_t)(lane >> 4) * 16u;
    const int brow = wn * 64 + ((lane >> 4) & 1) * 8 + (lane & 7);
    const uint32_t bkoff = (uint32_t)((lane >> 3) & 1) * 16u;

    float d[4][8][4];
#pragma unroll
    for (int i = 0; i < 4; i++)
#pragma unroll
        for (int j = 0; j < 8; j++)
#pragma unroll
            for (int q = 0; q < 4; q++) d[i][j][q] = 0.f;

#pragma unroll
    for (int c = 0; c < 3; c++) {
        uint32_t ab = sb0 + c * STG;
        uint32_t bb = ab + ASTG;
#pragma unroll
        for (int r = 0; r < 4; r++)
            cp16(ab + swA[r], Asrc + r * rstride + (size_t)c * 64);
#pragma unroll
        for (int r = 0; r < 8; r++)
            cp16(bb + swB[r], Bsrc + r * rstride + (size_t)c * 64);
        CP_COMMIT();
    }

    for (int c = 0; c < NC; ++c) {
        CP_WAIT2();
        __syncthreads();

        int slot = c & 3;
        uint32_t sA = sb0 + slot * STG;
        uint32_t sB = sA + ASTG;

#pragma unroll
        for (int ks = 0; ks < 4; ks++) {
            uint32_t kb = (uint32_t)ks * 32u;
            uint32_t a[4][4], bq[4][4];
#pragma unroll
            for (int i = 0; i < 4; i++) {
                uint32_t addr = sA + sw128((uint32_t)(arow + 16 * i) * 128u + kb + akoff);
                LDSM_X4(a[i][0], a[i][1], a[i][2], a[i][3], addr);
            }
#pragma unroll
            for (int j = 0; j < 4; j++) {
                uint32_t addr = sB + sw128((uint32_t)(brow + 16 * j) * 128u + kb + bkoff);
                LDSM_X4(bq[j][0], bq[j][1], bq[j][2], bq[j][3], addr);
            }
#pragma unroll
            for (int i = 0; i < 4; i++) {
#pragma unroll
                for (int j = 0; j < 4; j++) {
                    if (F16) {
                        MMA_F16(d[i][2 * j],     a[i], bq[j][0], bq[j][1]);
                        MMA_F16(d[i][2 * j + 1], a[i], bq[j][2], bq[j][3]);
                    } else {
                        MMA_BF16(d[i][2 * j],     a[i], bq[j][0], bq[j][1]);
                        MMA_BF16(d[i][2 * j + 1], a[i], bq[j][2], bq[j][3]);
                    }
                }
            }
        }

        int cl = c + 3;
        if (cl < NC) {
            int ls = cl & 3;
            uint32_t ab = sb0 + ls * STG;
            uint32_t bb = ab + ASTG;
#pragma unroll
            for (int r = 0; r < 4; r++)
                cp16(ab + swA[r], Asrc + r * rstride + (size_t)cl * 64);
#pragma unroll
            for (int r = 0; r < 8; r++)
                cp16(bb + swB[r], Bsrc + r * rstride + (size_t)cl * 64);
            CP_COMMIT();
        }
    }

    const int erow = lane >> 2;
    const int ecol = (lane & 3) * 2;
#pragma unroll
    for (int i = 0; i < 4; i++) {
        int r0 = m0 + wm * 64 + i * 16 + erow;
#pragma unroll
        for (int j = 0; j < 8; j++) {
            int cbase = wn * 64 + j * 8 + ecol;
            float bz0 = sbias[cbase], bz1 = sbias[cbase + 1];
            float2 v0 = { d[i][j][0] + bz0, d[i][j][1] + bz1 };
            float2 v1 = { d[i][j][2] + bz0, d[i][j][3] + bz1 };
            *(float2*)(C + (size_t)r0 * Ncols + n0 + cbase)       = v0;
            *(float2*)(C + (size_t)(r0 + 8) * Ncols + n0 + cbase) = v1;
        }
    }
}

// ---------------- persistent LSTM scan v12 (v11 + fp16 [hi|lo] fused h writer) ----------------
__global__ __launch_bounds__(256, 1)
void lstm_seq(const float* __restrict__ Whh, const float* __restrict__ xg,
              const float* __restrict__ c0, __half* __restrict__ a2h_out,
              float* __restrict__ c_out, int T)
{
    __shared__ ulonglong2 sh2[256];
    __shared__ float sp[8][33];

    const int tid  = threadIdx.x;
    const int warp = tid >> 5;
    const int lane = tid & 31;
    const int cta  = blockIdx.x;
    const int g    = lane >> 3;
    const int jj   = lane & 7;
    const int row  = g * HID + cta * 8 + jj;
    const int u8   = cta * 8 + (lane & 7);
    const int rep0 = lane >> 3;

    ulonglong2 w2[32];
    {
        const ulonglong2* wp =
            (const ulonglong2*)(Whh + (size_t)row * HID + warp * 128);
#pragma unroll
        for (int i = 0; i < 32; i++) w2[i] = wp[i];
    }

    float creg = 0.f;
    if (warp == 0) creg = c0[u8];
    unsigned* ctr = &g_ctr;

    const float* xgp = xg + (size_t)g * HID + cta * 8 + jj;
    float xgv_next = 0.f;
    if (tid < 32) xgv_next = __ldg(xgp);

    const ulonglong2* hsrc0 = ((const ulonglong2*)g_hrep[0][cta & 7]) + tid;
    const ulonglong2* hsrc1 = ((const ulonglong2*)g_hrep[1][cta & 7]) + tid;

    float p_hnew = 0.f;

    for (int t = 0; t < T; ++t) {
        sh2[tid] = __ldcg((t & 1) ? hsrc1 : hsrc0);
        float xgv = xgv_next;
        if (tid < 32 && t + 1 < T)
            xgv_next = __ldg(xgp + (size_t)(t + 1) * G4);

        // fused fp16 [hi|lo] write of h (from last iter) — hidden under LDG
        if (a2h_out && warp == 0 && lane < 8 && t > 0) {
            __half hhi = __float2half_rn(p_hnew);
            __half hlo = __float2half_rn(p_hnew - __half2float(hhi));
            size_t rb = (size_t)(t - 1) * K2H;
            a2h_out[rb + u8]       = hhi;
            a2h_out[rb + HID + u8] = hlo;
        }
        __syncwarp();

        ull a0 = 0, a1 = 0, a2 = 0, a3 = 0;
        const ulonglong2* hp = sh2 + warp * 32;
#pragma unroll
        for (int j = 0; j < 32; j += 2) {
            ulonglong2 ha = hp[j];
            ulonglong2 hb = hp[j + 1];
            FMA2(a0, w2[j].x, ha.x);
            FMA2(a1, w2[j].y, ha.y);
            FMA2(a2, w2[j + 1].x, hb.x);
            FMA2(a3, w2[j + 1].y, hb.y);
        }
        ull t01, t23, tt;
        ADD2(t01, a0, a1);
        ADD2(t23, a2, a3);
        ADD2(tt, t01, t23);
        uint32_t lo, hi;
        asm("mov.b64 {%0, %1}, %2;" : "=r"(lo), "=r"(hi) : "l"(tt));
        sp[warp][lane] = __uint_as_float(lo) + __uint_as_float(hi);
        __syncthreads();

        if (warp == 0) {
            float s = xgv;
#pragma unroll
            for (int w = 0; w < 8; w++) s += sp[w][lane];
            float act = (g == 2) ? tanh_apx(s) : sigf(s);
            float ai = __shfl_sync(0xffffffffu, act, lane & 7);
            float af = __shfl_sync(0xffffffffu, act, 8 + (lane & 7));
            float az = __shfl_sync(0xffffffffu, act, 16 + (lane & 7));
            float ao = __shfl_sync(0xffffffffu, act, 24 + (lane & 7));

            creg = af * creg + ai * az;
            float hnew = ao * tanh_apx(creg);
            p_hnew = hnew;

            float* outb = &g_hrep[(t + 1) & 1][0][0];
            outb[(size_t)rep0 * HID + u8]       = hnew;
            outb[(size_t)(rep0 + 4) * HID + u8] = hnew;

            __syncwarp();
            if (lane == 0) {
                unsigned old;
                asm volatile("atom.acq_rel.gpu.global.add.u32 %0, [%1], 1;"
                             : "=r"(old) : "l"(ctr) : "memory");
                unsigned tgt = (unsigned)(t + 1) * (unsigned)NCTA;
                if (old + 1u != tgt) {
                    unsigned v;
                    do {
                        asm volatile("ld.acquire.gpu.global.u32 %0, [%1];"
                                     : "=r"(v) : "l"(ctr) : "memory");
                    } while (v < tgt);
                }
            }
        }
        __syncthreads();
    }

    if (warp == 0 && lane < 8) {
        if (a2h_out) {
            __half hhi = __float2half_rn(p_hnew);
            __half hlo = __float2half_rn(p_hnew - __half2float(hhi));
            size_t rb = (size_t)(T - 1) * K2H;
            a2h_out[rb + u8]       = hhi;
            a2h_out[rb + HID + u8] = hlo;
        }
        if (c_out) c_out[u8] = creg;
    }
}

// ---------------- launch ----------------
template<bool F16>
static void launch_gemm(const void* A, const void* B,
                        const float* b1, const float* b2, float* C,
                        int M, int N, int K3, int GN)
{
    int Mt = M / 128, Nt = N / 256;
    cudaFuncSetAttribute(gemm_mma3<F16>, cudaFuncAttributeMaxDynamicSharedMemorySize, GEMM_SMEM);
    gemm_mma3<F16><<<Mt * Nt, 256, GEMM_SMEM>>>(
        (const __nv_bfloat16*)A, (const __nv_bfloat16*)B, b1, b2, C, Mt, K3, N, GN);
}

extern "C" void kernel_launch(void* const* d_in, const int* in_sizes, int n_in,
                              void* d_out, int out_size)
{
    const int*   e1       = (const int*)d_in[0];
    const int*   gt       = (const int*)d_in[1];
    const float* emb_i    = (const float*)d_in[2];
    const float* emb_o    = (const float*)d_in[3];
    const float* enc_Wih  = (const float*)d_in[4];
    const float* enc_Whh  = (const float*)d_in[5];
    const float* enc_bih  = (const float*)d_in[6];
    const float* enc_bhh  = (const float*)d_in[7];
    const float* dec_Wih  = (const float*)d_in[8];
    const float* dec_Whh  = (const float*)d_in[9];
    const float* dec_bih  = (const float*)d_in[10];
    const float* dec_bhh  = (const float*)d_in[11];
    const float* outW     = (const float*)d_in[12];
    const float* outb     = (const float*)d_in[13];
    float*       out      = (float*)d_out;

    float *xge, *xgd, *cenc, *czero;
    int* didx;
    __nv_bfloat16 *a3e, *a3d, *w3e, *w3d;
    __half *b2o, *a2h;
    cudaGetSymbolAddress((void**)&xge,   g_xg_enc);
    cudaGetSymbolAddress((void**)&xgd,   g_xg_dec);
    cudaGetSymbolAddress((void**)&cenc,  g_cenc);
    cudaGetSymbolAddress((void**)&czero, g_czero);
    cudaGetSymbolAddress((void**)&didx,  g_decidx);
    cudaGetSymbolAddress((void**)&a3e,   g_A3e);
    cudaGetSymbolAddress((void**)&a3d,   g_A3d);
    cudaGetSymbolAddress((void**)&w3e,   g_W3e);
    cudaGetSymbolAddress((void**)&w3d,   g_W3d);
    cudaGetSymbolAddress((void**)&b2o,   g_B2o);
    cudaGetSymbolAddress((void**)&a2h,   g_A2h);

    init0_kernel<<<8, 256>>>(gt);

    // conversions
    {
        long t1 = (long)G4 * EMB;
        conv_split<<<(int)(t1 / 4 / 256), 256>>>(enc_Wih, nullptr, w3e, EMB, t1, 1);
        conv_split<<<(int)(t1 / 4 / 256), 256>>>(dec_Wih, nullptr, w3d, EMB, t1, 1);
        long t2 = (long)OSIZE * HID;
        conv_dup_f16<<<(int)(t2 / 4 / 256), 256>>>(outW, b2o, HID, t2);
        long t3 = (long)TLEN * EMB;
        conv_split<<<(int)(t3 / 4 / 256), 256>>>(emb_i, e1,   a3e, EMB, t3, 0);
        conv_split<<<(int)(t3 / 4 / 256), 256>>>(emb_o, didx, a3d, EMB, t3, 0);
    }

    // x-gates (bf16 3-split, unchanged)
    launch_gemm<false>(a3e, w3e, enc_bih, enc_bhh, xge, TLEN, G4, K3E, 16);
    launch_gemm<false>(a3d, w3d, dec_bih, dec_bhh, xgd, TLEN, G4, K3E, 16);

    // encoder scan (keeps final cell state)
    lstm_seq<<<NCTA, 256>>>(enc_Whh, xge, czero, nullptr, cenc, TLEN);
    init1_kernel<<<4, 256>>>();
    // decoder scan — writes fp16 [hi|lo] h panel directly
    lstm_seq<<<NCTA, 256>>>(dec_Whh, xgd, cenc, a2h, nullptr, TLEN);

    // logits: fp16 2-split, K = 2048
    launch_gemm<true>(a2h, b2o, outb, nullptr, out, TLEN, OSIZE, K2H, 25);
}